// round 4
// baseline (speedup 1.0000x reference)
#include <cuda_runtime.h>

#define K_B 4
#define K_S 2048
#define K_D 1024
#define K_H 16
#define K_DH 64
#define K_ROWS (K_B * K_S)   // 8192

// Scratch (device globals: allocation-free per harness rules)
__device__ float g_Q[K_ROWS * K_D];
__device__ float g_K[K_ROWS * K_D];
__device__ float g_V[K_ROWS * K_D];
__device__ float g_C[K_ROWS * K_D];

// ---------------------------------------------------------------------------
// tf32 helpers
// ---------------------------------------------------------------------------
__device__ __forceinline__ unsigned f2tf(float f) {
    unsigned u;
    asm("cvt.rna.tf32.f32 %0, %1;" : "=r"(u) : "f"(f));
    return u;
}

__device__ __forceinline__ void mma_tf32(float* d, const uint4 a, unsigned b0, unsigned b1) {
    asm volatile(
        "mma.sync.aligned.m16n8k8.row.col.f32.tf32.tf32.f32 "
        "{%0,%1,%2,%3}, {%4,%5,%6,%7}, {%8,%9}, {%0,%1,%2,%3};\n"
        : "+f"(d[0]), "+f"(d[1]), "+f"(d[2]), "+f"(d[3])
        : "r"(a.x), "r"(a.y), "r"(a.z), "r"(a.w), "r"(b0), "r"(b1));
}

// m16n8k8 tf32 fragment maps:
// A element (r,c): lane=(r&7)*4+(c&3), reg=((r>>3)&1)+2*((c>>2)&1)
// B element (k,n): lane=(n&7)*4+(k&3), reg=(k>>2)&1
// C element: rows lane>>2, lane>>2+8; cols (lane&3)*2, +1

// ---------------------------------------------------------------------------
// GEMM: out = x @ W^T + bias. M=8192, N=1024, K=1024.
// BM=BN=128, BK=32, 256 threads (8 warps), warp tile 32x64.
// Double-buffered smem; B-fragments paired (2 k-tiles per uint4).
// Dynamic smem: 2 * (16KB A + 16KB B) = 64KB.
// ---------------------------------------------------------------------------
extern __shared__ unsigned smem_dyn[];

__global__ __launch_bounds__(256) void gemm_tc(
    const float* __restrict__ x, const float* __restrict__ W,
    const float* __restrict__ bias, float* __restrict__ out)
{
    // As[buf]: [mt 8][kt 4][lane 32][reg 4]  (4096 words)
    // Bs[buf]: [nt 16][pair 2][lane 32][4]   (4096 words)
    unsigned* As[2] = { smem_dyn,         smem_dyn + 8192  };
    unsigned* Bs[2] = { smem_dyn + 4096,  smem_dyn + 12288 };

    const int tid  = threadIdx.x;
    const int lane = tid & 31;
    const int warp = tid >> 5;
    const int wm = warp >> 1;   // 0..3
    const int wn = warp & 1;    // 0..1
    const int rowBase = blockIdx.y * 128;
    const int colBase = blockIdx.x * 128;

    float acc[2][8][4];
    #pragma unroll
    for (int mi = 0; mi < 2; mi++)
        #pragma unroll
        for (int ni = 0; ni < 8; ni++)
            #pragma unroll
            for (int v = 0; v < 4; v++) acc[mi][ni][v] = 0.f;

    float4 pa[4], pb[4];
    #pragma unroll
    for (int i = 0; i < 4; i++) {
        int li = tid + i * 256;
        int m = li >> 3;
        int k = (li & 7) * 4;
        pa[i] = *(const float4*)&x[(size_t)(rowBase + m) * K_D + k];
        pb[i] = *(const float4*)&W[(size_t)(colBase + m) * K_D + k];
    }

    for (int k0 = 0; k0 < K_D; k0 += 32) {
        const int buf = (k0 >> 5) & 1;
        unsigned* Ab = As[buf];
        unsigned* Bb = Bs[buf];
        #pragma unroll
        for (int i = 0; i < 4; i++) {
            int li = tid + i * 256;
            int m = li >> 3;
            int kk = (li & 7) * 4;
            float av[4] = {pa[i].x, pa[i].y, pa[i].z, pa[i].w};
            float bv[4] = {pb[i].x, pb[i].y, pb[i].z, pb[i].w};
            #pragma unroll
            for (int j = 0; j < 4; j++) {
                int k = kk + j;
                int ia = (((m >> 4) * 4 + (k >> 3)) * 32 + ((m & 7) * 4 + (k & 3))) * 4
                         + (((m >> 3) & 1) + 2 * ((k >> 2) & 1));
                Ab[ia] = f2tf(av[j]);
                int kt = k >> 3;
                int ib = ((((m >> 3) * 2 + (kt >> 1)) * 32 + ((m & 7) * 4 + (k & 3))) * 4)
                         + (kt & 1) * 2 + ((k >> 2) & 1);
                Bb[ib] = f2tf(bv[j]);
            }
        }
        __syncthreads();

        if (k0 + 32 < K_D) {
            #pragma unroll
            for (int i = 0; i < 4; i++) {
                int li = tid + i * 256;
                int m = li >> 3;
                int k = (li & 7) * 4;
                pa[i] = *(const float4*)&x[(size_t)(rowBase + m) * K_D + k0 + 32 + k];
                pb[i] = *(const float4*)&W[(size_t)(colBase + m) * K_D + k0 + 32 + k];
            }
        }

        const uint4* A4 = (const uint4*)Ab;
        const uint4* B4 = (const uint4*)Bb;
        #pragma unroll
        for (int p = 0; p < 2; p++) {
            uint4 afr[2][2];
            #pragma unroll
            for (int mi = 0; mi < 2; mi++) {
                afr[mi][0] = A4[((wm * 2 + mi) * 4 + 2 * p) * 32 + lane];
                afr[mi][1] = A4[((wm * 2 + mi) * 4 + 2 * p + 1) * 32 + lane];
            }
            #pragma unroll
            for (int ni = 0; ni < 8; ni++) {
                uint4 bb = B4[((wn * 8 + ni) * 2 + p) * 32 + lane];
                #pragma unroll
                for (int mi = 0; mi < 2; mi++) {
                    mma_tf32(acc[mi][ni], afr[mi][0], bb.x, bb.y);
                    mma_tf32(acc[mi][ni], afr[mi][1], bb.z, bb.w);
                }
            }
        }
        __syncthreads();
    }

    #pragma unroll
    for (int mi = 0; mi < 2; mi++) {
        int row0 = rowBase + (wm * 2 + mi) * 16 + (lane >> 2);
        #pragma unroll
        for (int ni = 0; ni < 8; ni++) {
            int col = colBase + (wn * 8 + ni) * 8 + (lane & 3) * 2;
            float b0 = __ldg(&bias[col]);
            float b1 = __ldg(&bias[col + 1]);
            float2 v0 = make_float2(acc[mi][ni][0] + b0, acc[mi][ni][1] + b1);
            float2 v1 = make_float2(acc[mi][ni][2] + b0, acc[mi][ni][3] + b1);
            *(float2*)&out[(size_t)row0 * K_D + col] = v0;
            *(float2*)&out[(size_t)(row0 + 8) * K_D + col] = v1;
        }
    }
}

// ---------------------------------------------------------------------------
// Flash attention, tf32 tensor cores, P kept in registers (shuffle re-permute).
// Grid: (B*H, S/128). Block: 256 threads (8 warps).
// Br=128 (16 rows/warp), Bc=64, Dh=64.
// Dynamic smem 96KB: Qs(32KB, A-frag) + 2 x [Ks(16KB) + Vts(16KB)] paired B-frags.
// ---------------------------------------------------------------------------
__global__ __launch_bounds__(256) void flash_tc(
    const float* __restrict__ Q, const float* __restrict__ K,
    const float* __restrict__ V, float* __restrict__ O)
{
    unsigned* Qs = smem_dyn;                         // [mt 8][kt 8][32][4] = 8192 w
    unsigned* KsB[2] = { smem_dyn + 8192,  smem_dyn + 16384 };  // [nt 8][pair 4][32][4] = 4096 w
    unsigned* VtB[2] = { smem_dyn + 12288, smem_dyn + 20480 };  // [dt 8][pair 4][32][4] = 4096 w

    const int tid  = threadIdx.x;
    const int lane = tid & 31;
    const int warp = tid >> 5;

    const int bh = blockIdx.x;
    const int b = bh / K_H, h = bh % K_H;
    const int qbase = blockIdx.y * 128;
    const size_t base = (size_t)b * K_S * K_D + (size_t)h * K_DH;
    const float scale = 0.125f;   // 1/sqrt(64)

    // Load Q tile (128x64) into A-frag layout, pre-scaled
    #pragma unroll
    for (int i = 0; i < 8; i++) {
        int li = tid + i * 256;
        int m = li >> 4;
        int k = (li & 15) * 4;
        float4 v = *(const float4*)&Q[base + (size_t)(qbase + m) * K_D + k];
        float qv[4] = {v.x * scale, v.y * scale, v.z * scale, v.w * scale};
        #pragma unroll
        for (int j = 0; j < 4; j++) {
            int kk = k + j;
            int ia = (((m >> 4) * 8 + (kk >> 3)) * 32 + ((m & 7) * 4 + (kk & 3))) * 4
                     + (((m >> 3) & 1) + 2 * ((kk >> 2) & 1));
            Qs[ia] = f2tf(qv[j]);
        }
    }

    float accO[8][4];
    #pragma unroll
    for (int ni = 0; ni < 8; ni++)
        #pragma unroll
        for (int v = 0; v < 4; v++) accO[ni][v] = 0.f;

    float m0 = -1e30f, m1 = -1e30f, l0 = 0.f, l1 = 0.f;

    // Prefetch first K/V tile: 64 rows x 64 dims = 1024 float4 per tensor
    // => 4 float4 per thread per tensor (THIS was the R3 bug: only 2 loaded)
    float4 kpre[4], vpre[4];
    #pragma unroll
    for (int i = 0; i < 4; i++) {
        int li = tid + i * 256;
        int n = li >> 4;            // 0..63
        int k = (li & 15) * 4;      // 0..60
        kpre[i] = *(const float4*)&K[base + (size_t)n * K_D + k];
        vpre[i] = *(const float4*)&V[base + (size_t)n * K_D + k];
    }
    __syncthreads();   // Qs visible

    const int tq = lane & 3;
    const int s0l = (lane & ~3) | (tq >> 1);
    const int s1l = s0l + 2;
    const bool odd = tq & 1;

    for (int jt = 0; jt < K_S; jt += 64) {
        const int buf = (jt >> 6) & 1;
        unsigned* Ks  = KsB[buf];
        unsigned* Vts = VtB[buf];

        // Store K/V fragments (paired layout), full 64x64 tile
        #pragma unroll
        for (int i = 0; i < 4; i++) {
            int li = tid + i * 256;
            int n = li >> 4;           // kv row in tile (0..63)
            int kk = (li & 15) * 4;    // dim
            float kv[4] = {kpre[i].x, kpre[i].y, kpre[i].z, kpre[i].w};
            float vv[4] = {vpre[i].x, vpre[i].y, vpre[i].z, vpre[i].w};
            int ktv = n >> 3;          // V contraction k-tile (fixed per thread)
            #pragma unroll
            for (int j = 0; j < 4; j++) {
                int k = kk + j;   // dim index
                int kt = k >> 3;
                int ib = ((((n >> 3) * 4 + (kt >> 1)) * 32 + ((n & 7) * 4 + (k & 3))) * 4)
                         + (kt & 1) * 2 + ((k >> 2) & 1);
                Ks[ib] = f2tf(kv[j]);
                int iv = ((((k >> 3) * 4 + (ktv >> 1)) * 32 + ((k & 7) * 4 + (n & 3))) * 4)
                         + (ktv & 1) * 2 + ((n >> 2) & 1);
                Vts[iv] = f2tf(vv[j]);
            }
        }
        __syncthreads();

        if (jt + 64 < K_S) {
            #pragma unroll
            for (int i = 0; i < 4; i++) {
                int li = tid + i * 256;
                int n = li >> 4;
                int k = (li & 15) * 4;
                kpre[i] = *(const float4*)&K[base + (size_t)(jt + 64 + n) * K_D + k];
                vpre[i] = *(const float4*)&V[base + (size_t)(jt + 64 + n) * K_D + k];
            }
        }

        // ---- S = (Q*scale) K^T ----
        float accS[8][4];
        #pragma unroll
        for (int ni = 0; ni < 8; ni++)
            #pragma unroll
            for (int v = 0; v < 4; v++) accS[ni][v] = 0.f;

        const uint4* Q4 = (const uint4*)Qs;
        const uint4* K4 = (const uint4*)Ks;
        const uint4* V4 = (const uint4*)Vts;

        #pragma unroll
        for (int p = 0; p < 4; p++) {
            uint4 a0 = Q4[(warp * 8 + 2 * p) * 32 + lane];
            uint4 a1 = Q4[(warp * 8 + 2 * p + 1) * 32 + lane];
            #pragma unroll
            for (int ni = 0; ni < 8; ni++) {
                uint4 bb = K4[(ni * 4 + p) * 32 + lane];
                mma_tf32(accS[ni], a0, bb.x, bb.y);
                mma_tf32(accS[ni], a1, bb.z, bb.w);
            }
        }

        // ---- online softmax (rows lane>>2 and +8, quad-local) ----
        float mx0 = -1e30f, mx1 = -1e30f;
        #pragma unroll
        for (int ni = 0; ni < 8; ni++) {
            mx0 = fmaxf(mx0, fmaxf(accS[ni][0], accS[ni][1]));
            mx1 = fmaxf(mx1, fmaxf(accS[ni][2], accS[ni][3]));
        }
        mx0 = fmaxf(mx0, __shfl_xor_sync(0xffffffffu, mx0, 1));
        mx0 = fmaxf(mx0, __shfl_xor_sync(0xffffffffu, mx0, 2));
        mx1 = fmaxf(mx1, __shfl_xor_sync(0xffffffffu, mx1, 1));
        mx1 = fmaxf(mx1, __shfl_xor_sync(0xffffffffu, mx1, 2));

        float mn0 = fmaxf(m0, mx0);
        float mn1 = fmaxf(m1, mx1);
        float alpha0 = __expf(m0 - mn0);
        float alpha1 = __expf(m1 - mn1);
        m0 = mn0; m1 = mn1;

        float sum0 = 0.f, sum1 = 0.f;
        #pragma unroll
        for (int ni = 0; ni < 8; ni++) {
            accS[ni][0] = __expf(accS[ni][0] - mn0);
            accS[ni][1] = __expf(accS[ni][1] - mn0);
            accS[ni][2] = __expf(accS[ni][2] - mn1);
            accS[ni][3] = __expf(accS[ni][3] - mn1);
            sum0 += accS[ni][0] + accS[ni][1];
            sum1 += accS[ni][2] + accS[ni][3];
        }
        sum0 += __shfl_xor_sync(0xffffffffu, sum0, 1);
        sum0 += __shfl_xor_sync(0xffffffffu, sum0, 2);
        sum1 += __shfl_xor_sync(0xffffffffu, sum1, 1);
        sum1 += __shfl_xor_sync(0xffffffffu, sum1, 2);
        l0 = l0 * alpha0 + sum0;
        l1 = l1 * alpha1 + sum1;

        #pragma unroll
        for (int ni = 0; ni < 8; ni++) {
            accO[ni][0] *= alpha0; accO[ni][1] *= alpha0;
            accO[ni][2] *= alpha1; accO[ni][3] *= alpha1;
        }

        // ---- O += P @ V : P A-frags built in-register via quad shuffles ----
        #pragma unroll
        for (int p = 0; p < 4; p++) {
            uint4 aP[2];
            #pragma unroll
            for (int s = 0; s < 2; s++) {
                const float* pr = accS[2 * p + s];
                float e0 = __shfl_sync(0xffffffffu, pr[0], s0l);
                float e1 = __shfl_sync(0xffffffffu, pr[1], s0l);
                float g0 = __shfl_sync(0xffffffffu, pr[2], s0l);
                float g1 = __shfl_sync(0xffffffffu, pr[3], s0l);
                float e2 = __shfl_sync(0xffffffffu, pr[0], s1l);
                float e3 = __shfl_sync(0xffffffffu, pr[1], s1l);
                float g2 = __shfl_sync(0xffffffffu, pr[2], s1l);
                float g3 = __shfl_sync(0xffffffffu, pr[3], s1l);
                aP[s].x = f2tf(odd ? e1 : e0);   // P[r0,  t]
                aP[s].y = f2tf(odd ? g1 : g0);   // P[r0+8,t]
                aP[s].z = f2tf(odd ? e3 : e2);   // P[r0,  t+4]
                aP[s].w = f2tf(odd ? g3 : g2);   // P[r0+8,t+4]
            }
            #pragma unroll
            for (int ni = 0; ni < 8; ni++) {
                uint4 vb = V4[(ni * 4 + p) * 32 + lane];
                mma_tf32(accO[ni], aP[0], vb.x, vb.y);
                mma_tf32(accO[ni], aP[1], vb.z, vb.w);
            }
        }
    }

    // Epilogue: normalize and write context
    float inv0 = 1.0f / l0;
    float inv1 = 1.0f / l1;
    int row0 = qbase + warp * 16 + (lane >> 2);
    #pragma unroll
    for (int ni = 0; ni < 8; ni++) {
        int col = ni * 8 + (lane & 3) * 2;
        float2 v0 = make_float2(accO[ni][0] * inv0, accO[ni][1] * inv0);
        float2 v1 = make_float2(accO[ni][2] * inv1, accO[ni][3] * inv1);
        *(float2*)&O[base + (size_t)row0 * K_D + col] = v0;
        *(float2*)&O[base + (size_t)(row0 + 8) * K_D + col] = v1;
    }
}

// ---------------------------------------------------------------------------
extern "C" void kernel_launch(void* const* d_in, const int* in_sizes, int n_in,
                              void* d_out, int out_size)
{
    const float* query = (const float*)d_in[0];
    const float* key   = (const float*)d_in[1];
    const float* value = (const float*)d_in[2];
    const float* Wq    = (const float*)d_in[3];
    const float* bq    = (const float*)d_in[4];
    const float* Wk    = (const float*)d_in[5];
    const float* bk    = (const float*)d_in[6];
    const float* Wv    = (const float*)d_in[7];
    const float* bv    = (const float*)d_in[8];
    const float* Wo    = (const float*)d_in[9];
    const float* bo    = (const float*)d_in[10];
    float* out = (float*)d_out;

    float *gq, *gk, *gv, *gc;
    cudaGetSymbolAddress((void**)&gq, g_Q);
    cudaGetSymbolAddress((void**)&gk, g_K);
    cudaGetSymbolAddress((void**)&gv, g_V);
    cudaGetSymbolAddress((void**)&gc, g_C);

    static bool attr_done = false;
    if (!attr_done) {
        cudaFuncSetAttribute(gemm_tc, cudaFuncAttributeMaxDynamicSharedMemorySize, 65536);
        cudaFuncSetAttribute(flash_tc, cudaFuncAttributeMaxDynamicSharedMemorySize, 98304);
        attr_done = true;
    }

    dim3 gemm_grid(K_D / 128, K_ROWS / 128);   // (8, 64)
    gemm_tc<<<gemm_grid, 256, 65536>>>(query, Wq, bq, gq);
    gemm_tc<<<gemm_grid, 256, 65536>>>(key,   Wk, bk, gk);
    gemm_tc<<<gemm_grid, 256, 65536>>>(value, Wv, bv, gv);

    dim3 attn_grid(K_B * K_H, K_S / 128);      // (64, 16)
    flash_tc<<<attn_grid, 256, 98304>>>(gq, gk, gv, gc);

    gemm_tc<<<gemm_grid, 256, 65536>>>(gc, Wo, bo, out);
}

// round 5
// speedup vs baseline: 1.1054x; 1.1054x over previous
#include <cuda_runtime.h>

#define K_B 4
#define K_S 2048
#define K_D 1024
#define K_H 16
#define K_DH 64
#define K_ROWS (K_B * K_S)   // 8192

// Scratch (device globals: allocation-free per harness rules)
__device__ float g_Q[K_ROWS * K_D];
__device__ float g_K[K_ROWS * K_D];
__device__ float g_V[K_ROWS * K_D];
__device__ float g_C[K_ROWS * K_D];

// ---------------------------------------------------------------------------
// tf32 helpers
// ---------------------------------------------------------------------------
__device__ __forceinline__ unsigned f2tf(float f) {
    unsigned u;
    asm("cvt.rna.tf32.f32 %0, %1;" : "=r"(u) : "f"(f));
    return u;
}

__device__ __forceinline__ void mma_tf32_u2(float* d, const uint4 a, const uint2 b) {
    asm volatile(
        "mma.sync.aligned.m16n8k8.row.col.f32.tf32.tf32.f32 "
        "{%0,%1,%2,%3}, {%4,%5,%6,%7}, {%8,%9}, {%0,%1,%2,%3};\n"
        : "+f"(d[0]), "+f"(d[1]), "+f"(d[2]), "+f"(d[3])
        : "r"(a.x), "r"(a.y), "r"(a.z), "r"(a.w), "r"(b.x), "r"(b.y));
}

__device__ __forceinline__ void mma_tf32(float* d, const uint4 a, unsigned b0, unsigned b1) {
    asm volatile(
        "mma.sync.aligned.m16n8k8.row.col.f32.tf32.tf32.f32 "
        "{%0,%1,%2,%3}, {%4,%5,%6,%7}, {%8,%9}, {%0,%1,%2,%3};\n"
        : "+f"(d[0]), "+f"(d[1]), "+f"(d[2]), "+f"(d[3])
        : "r"(a.x), "r"(a.y), "r"(a.z), "r"(a.w), "r"(b0), "r"(b1));
}

// m16n8k8 tf32 fragment maps:
// A element (r,c): lane=(r&7)*4+(c&3), reg=((r>>3)&1)+2*((c>>2)&1)
// B element (k,n): lane=(n&7)*4+(k&3), reg=(k>>2)&1
// C element: rows lane>>2, lane>>2+8; cols (lane&3)*2, +1

// ---------------------------------------------------------------------------
// GEMM (R2 version, verbatim — known-good 226us/call):
// out = x @ W^T + bias. BM=BN=128, BK=32, 256 threads, warp tile 32x64.
// Static 32KB smem, register prefetch, fragment-layout staging.
// ---------------------------------------------------------------------------
__global__ __launch_bounds__(256) void gemm_tc(
    const float* __restrict__ x, const float* __restrict__ W,
    const float* __restrict__ bias, float* __restrict__ out)
{
    __shared__ unsigned As[8 * 4 * 32 * 4];   // [mt 8][kt 4][lane 32][reg 4] 16KB
    __shared__ unsigned Bs[16 * 4 * 32 * 2];  // [nt16][kt 4][lane 32][reg 2] 16KB

    const int tid  = threadIdx.x;
    const int lane = tid & 31;
    const int warp = tid >> 5;
    const int wm = warp >> 1;   // 0..3
    const int wn = warp & 1;    // 0..1
    const int rowBase = blockIdx.y * 128;
    const int colBase = blockIdx.x * 128;

    float acc[2][8][4];
    #pragma unroll
    for (int mi = 0; mi < 2; mi++)
        #pragma unroll
        for (int ni = 0; ni < 8; ni++)
            #pragma unroll
            for (int v = 0; v < 4; v++) acc[mi][ni][v] = 0.f;

    float4 pa[4], pb[4];
    #pragma unroll
    for (int i = 0; i < 4; i++) {
        int li = tid + i * 256;
        int m = li >> 3;
        int k = (li & 7) * 4;
        pa[i] = *(const float4*)&x[(size_t)(rowBase + m) * K_D + k];
        pb[i] = *(const float4*)&W[(size_t)(colBase + m) * K_D + k];
    }

    const uint4* As4 = (const uint4*)As;
    const uint2* Bs2 = (const uint2*)Bs;

    for (int k0 = 0; k0 < K_D; k0 += 32) {
        __syncthreads();   // previous compute done before overwrite
        #pragma unroll
        for (int i = 0; i < 4; i++) {
            int li = tid + i * 256;
            int m = li >> 3;
            int kk = (li & 7) * 4;
            float av[4] = {pa[i].x, pa[i].y, pa[i].z, pa[i].w};
            float bv[4] = {pb[i].x, pb[i].y, pb[i].z, pb[i].w};
            #pragma unroll
            for (int j = 0; j < 4; j++) {
                int k = kk + j;
                int ia = (((m >> 4) * 4 + (k >> 3)) * 32 + ((m & 7) * 4 + (k & 3))) * 4
                         + (((m >> 3) & 1) + 2 * ((k >> 2) & 1));
                As[ia] = f2tf(av[j]);
                int ib = (((m >> 3) * 4 + (k >> 3)) * 32 + ((m & 7) * 4 + (k & 3))) * 2
                         + ((k >> 2) & 1);
                Bs[ib] = f2tf(bv[j]);
            }
        }
        __syncthreads();

        if (k0 + 32 < K_D) {
            #pragma unroll
            for (int i = 0; i < 4; i++) {
                int li = tid + i * 256;
                int m = li >> 3;
                int k = (li & 7) * 4;
                pa[i] = *(const float4*)&x[(size_t)(rowBase + m) * K_D + k0 + 32 + k];
                pb[i] = *(const float4*)&W[(size_t)(colBase + m) * K_D + k0 + 32 + k];
            }
        }

        #pragma unroll
        for (int kt = 0; kt < 4; kt++) {
            uint4 afr[2];
            #pragma unroll
            for (int mi = 0; mi < 2; mi++)
                afr[mi] = As4[((wm * 2 + mi) * 4 + kt) * 32 + lane];
            #pragma unroll
            for (int ni = 0; ni < 8; ni++) {
                uint2 bfr = Bs2[((wn * 8 + ni) * 4 + kt) * 32 + lane];
                #pragma unroll
                for (int mi = 0; mi < 2; mi++)
                    mma_tf32_u2(acc[mi][ni], afr[mi], bfr);
            }
        }
    }

    #pragma unroll
    for (int mi = 0; mi < 2; mi++) {
        int row0 = rowBase + (wm * 2 + mi) * 16 + (lane >> 2);
        #pragma unroll
        for (int ni = 0; ni < 8; ni++) {
            int col = colBase + (wn * 8 + ni) * 8 + (lane & 3) * 2;
            float b0 = __ldg(&bias[col]);
            float b1 = __ldg(&bias[col + 1]);
            float2 v0 = make_float2(acc[mi][ni][0] + b0, acc[mi][ni][1] + b1);
            float2 v1 = make_float2(acc[mi][ni][2] + b0, acc[mi][ni][3] + b1);
            *(float2*)&out[(size_t)row0 * K_D + col] = v0;
            *(float2*)&out[(size_t)(row0 + 8) * K_D + col] = v1;
        }
    }
}

// ---------------------------------------------------------------------------
// Flash attention, tf32, P in registers, Bc=32 for 2 CTAs/SM.
// Grid: (B*H, S/128). Block: 256 threads (8 warps), 16 q-rows per warp.
// Dynamic smem 64KB: Qs(32KB A-frag) + 2 x [Ks(8KB) + Vts(8KB)] paired B-frags.
// ---------------------------------------------------------------------------
extern __shared__ unsigned smem_dyn[];

__global__ __launch_bounds__(256, 2) void flash_tc(
    const float* __restrict__ Q, const float* __restrict__ K,
    const float* __restrict__ V, float* __restrict__ O)
{
    unsigned* Qs = smem_dyn;                                      // [mt 8][kt 8][32][4] = 8192 w
    unsigned* KsB[2] = { smem_dyn + 8192,  smem_dyn + 12288 };    // [nt 4][kpair 4][32][4] = 2048 w
    unsigned* VtB[2] = { smem_dyn + 10240, smem_dyn + 14336 };    // [dt 8][pair 2][32][4]  = 2048 w

    const int tid  = threadIdx.x;
    const int lane = tid & 31;
    const int warp = tid >> 5;

    const int bh = blockIdx.x;
    const int b = bh / K_H, h = bh % K_H;
    const int qbase = blockIdx.y * 128;
    const size_t base = (size_t)b * K_S * K_D + (size_t)h * K_DH;
    const float scale = 0.125f;   // 1/sqrt(64)

    // Load Q tile (128x64) into A-frag layout, pre-scaled
    #pragma unroll
    for (int i = 0; i < 8; i++) {
        int li = tid + i * 256;
        int m = li >> 4;
        int k = (li & 15) * 4;
        float4 v = *(const float4*)&Q[base + (size_t)(qbase + m) * K_D + k];
        float qv[4] = {v.x * scale, v.y * scale, v.z * scale, v.w * scale};
        #pragma unroll
        for (int j = 0; j < 4; j++) {
            int kk = k + j;
            int ia = (((m >> 4) * 8 + (kk >> 3)) * 32 + ((m & 7) * 4 + (kk & 3))) * 4
                     + (((m >> 3) & 1) + 2 * ((kk >> 2) & 1));
            Qs[ia] = f2tf(qv[j]);
        }
    }

    float accO[8][4];
    #pragma unroll
    for (int ni = 0; ni < 8; ni++)
        #pragma unroll
        for (int v = 0; v < 4; v++) accO[ni][v] = 0.f;

    float m0 = -1e30f, m1 = -1e30f, l0 = 0.f, l1 = 0.f;

    // Prefetch first K/V tile: 32 rows x 64 dims = 512 float4 per tensor
    // => 2 float4 per thread per tensor
    float4 kpre[2], vpre[2];
    #pragma unroll
    for (int i = 0; i < 2; i++) {
        int li = tid + i * 256;
        int n = li >> 4;            // 0..31
        int k = (li & 15) * 4;      // 0..60
        kpre[i] = *(const float4*)&K[base + (size_t)n * K_D + k];
        vpre[i] = *(const float4*)&V[base + (size_t)n * K_D + k];
    }
    __syncthreads();   // Qs visible

    const int tq = lane & 3;
    const int s0l = (lane & ~3) | (tq >> 1);
    const int s1l = s0l + 2;
    const bool odd = tq & 1;

    for (int jt = 0; jt < K_S; jt += 32) {
        const int buf = (jt >> 5) & 1;
        unsigned* Ks  = KsB[buf];
        unsigned* Vts = VtB[buf];

        // Store K/V fragments (paired layout), 32x64 tile
        #pragma unroll
        for (int i = 0; i < 2; i++) {
            int li = tid + i * 256;
            int n = li >> 4;           // kv row in tile (0..31)
            int kk = (li & 15) * 4;    // dim
            float kv[4] = {kpre[i].x, kpre[i].y, kpre[i].z, kpre[i].w};
            float vv[4] = {vpre[i].x, vpre[i].y, vpre[i].z, vpre[i].w};
            int ktv = n >> 3;          // V contraction k-tile (0..3, fixed per thread)
            #pragma unroll
            for (int j = 0; j < 4; j++) {
                int k = kk + j;   // dim index (0..63)
                int kt = k >> 3;  // QK contraction k-tile (0..7)
                int ib = ((((n >> 3) * 4 + (kt >> 1)) * 32 + ((n & 7) * 4 + (k & 3))) * 4)
                         + (kt & 1) * 2 + ((k >> 2) & 1);
                Ks[ib] = f2tf(kv[j]);
                int iv = ((((k >> 3) * 2 + (ktv >> 1)) * 32 + ((k & 7) * 4 + (n & 3))) * 4)
                         + (ktv & 1) * 2 + ((n >> 2) & 1);
                Vts[iv] = f2tf(vv[j]);
            }
        }
        __syncthreads();

        if (jt + 32 < K_S) {
            #pragma unroll
            for (int i = 0; i < 2; i++) {
                int li = tid + i * 256;
                int n = li >> 4;
                int k = (li & 15) * 4;
                kpre[i] = *(const float4*)&K[base + (size_t)(jt + 32 + n) * K_D + k];
                vpre[i] = *(const float4*)&V[base + (size_t)(jt + 32 + n) * K_D + k];
            }
        }

        // ---- S = (Q*scale) K^T : warp tile 16 x 32 ----
        float accS[4][4];
        #pragma unroll
        for (int ni = 0; ni < 4; ni++)
            #pragma unroll
            for (int v = 0; v < 4; v++) accS[ni][v] = 0.f;

        const uint4* Q4 = (const uint4*)Qs;
        const uint4* K4 = (const uint4*)Ks;
        const uint4* V4 = (const uint4*)Vts;

        #pragma unroll
        for (int p = 0; p < 4; p++) {
            uint4 a0 = Q4[(warp * 8 + 2 * p) * 32 + lane];
            uint4 a1 = Q4[(warp * 8 + 2 * p + 1) * 32 + lane];
            #pragma unroll
            for (int ni = 0; ni < 4; ni++) {
                uint4 bb = K4[(ni * 4 + p) * 32 + lane];
                mma_tf32(accS[ni], a0, bb.x, bb.y);
                mma_tf32(accS[ni], a1, bb.z, bb.w);
            }
        }

        // ---- online softmax (rows lane>>2 and +8, quad-local) ----
        float mx0 = -1e30f, mx1 = -1e30f;
        #pragma unroll
        for (int ni = 0; ni < 4; ni++) {
            mx0 = fmaxf(mx0, fmaxf(accS[ni][0], accS[ni][1]));
            mx1 = fmaxf(mx1, fmaxf(accS[ni][2], accS[ni][3]));
        }
        mx0 = fmaxf(mx0, __shfl_xor_sync(0xffffffffu, mx0, 1));
        mx0 = fmaxf(mx0, __shfl_xor_sync(0xffffffffu, mx0, 2));
        mx1 = fmaxf(mx1, __shfl_xor_sync(0xffffffffu, mx1, 1));
        mx1 = fmaxf(mx1, __shfl_xor_sync(0xffffffffu, mx1, 2));

        float mn0 = fmaxf(m0, mx0);
        float mn1 = fmaxf(m1, mx1);
        float alpha0 = __expf(m0 - mn0);
        float alpha1 = __expf(m1 - mn1);
        m0 = mn0; m1 = mn1;

        float sum0 = 0.f, sum1 = 0.f;
        #pragma unroll
        for (int ni = 0; ni < 4; ni++) {
            accS[ni][0] = __expf(accS[ni][0] - mn0);
            accS[ni][1] = __expf(accS[ni][1] - mn0);
            accS[ni][2] = __expf(accS[ni][2] - mn1);
            accS[ni][3] = __expf(accS[ni][3] - mn1);
            sum0 += accS[ni][0] + accS[ni][1];
            sum1 += accS[ni][2] + accS[ni][3];
        }
        sum0 += __shfl_xor_sync(0xffffffffu, sum0, 1);
        sum0 += __shfl_xor_sync(0xffffffffu, sum0, 2);
        sum1 += __shfl_xor_sync(0xffffffffu, sum1, 1);
        sum1 += __shfl_xor_sync(0xffffffffu, sum1, 2);
        l0 = l0 * alpha0 + sum0;
        l1 = l1 * alpha1 + sum1;

        #pragma unroll
        for (int ni = 0; ni < 8; ni++) {
            accO[ni][0] *= alpha0; accO[ni][1] *= alpha0;
            accO[ni][2] *= alpha1; accO[ni][3] *= alpha1;
        }

        // ---- O += P @ V : P A-frags built in-register via quad shuffles ----
        #pragma unroll
        for (int p = 0; p < 2; p++) {
            uint4 aP[2];
            #pragma unroll
            for (int s = 0; s < 2; s++) {
                const float* pr = accS[2 * p + s];
                float e0 = __shfl_sync(0xffffffffu, pr[0], s0l);
                float e1 = __shfl_sync(0xffffffffu, pr[1], s0l);
                float g0 = __shfl_sync(0xffffffffu, pr[2], s0l);
                float g1 = __shfl_sync(0xffffffffu, pr[3], s0l);
                float e2 = __shfl_sync(0xffffffffu, pr[0], s1l);
                float e3 = __shfl_sync(0xffffffffu, pr[1], s1l);
                float g2 = __shfl_sync(0xffffffffu, pr[2], s1l);
                float g3 = __shfl_sync(0xffffffffu, pr[3], s1l);
                aP[s].x = f2tf(odd ? e1 : e0);   // P[r0,  t]
                aP[s].y = f2tf(odd ? g1 : g0);   // P[r0+8,t]
                aP[s].z = f2tf(odd ? e3 : e2);   // P[r0,  t+4]
                aP[s].w = f2tf(odd ? g3 : g2);   // P[r0+8,t+4]
            }
            #pragma unroll
            for (int ni = 0; ni < 8; ni++) {
                uint4 vb = V4[(ni * 2 + p) * 32 + lane];
                mma_tf32(accO[ni], aP[0], vb.x, vb.y);
                mma_tf32(accO[ni], aP[1], vb.z, vb.w);
            }
        }
    }

    // Epilogue: normalize and write context
    float inv0 = 1.0f / l0;
    float inv1 = 1.0f / l1;
    int row0 = qbase + warp * 16 + (lane >> 2);
    #pragma unroll
    for (int ni = 0; ni < 8; ni++) {
        int col = ni * 8 + (lane & 3) * 2;
        float2 v0 = make_float2(accO[ni][0] * inv0, accO[ni][1] * inv0);
        float2 v1 = make_float2(accO[ni][2] * inv1, accO[ni][3] * inv1);
        *(float2*)&O[base + (size_t)row0 * K_D + col] = v0;
        *(float2*)&O[base + (size_t)(row0 + 8) * K_D + col] = v1;
    }
}

// ---------------------------------------------------------------------------
extern "C" void kernel_launch(void* const* d_in, const int* in_sizes, int n_in,
                              void* d_out, int out_size)
{
    const float* query = (const float*)d_in[0];
    const float* key   = (const float*)d_in[1];
    const float* value = (const float*)d_in[2];
    const float* Wq    = (const float*)d_in[3];
    const float* bq    = (const float*)d_in[4];
    const float* Wk    = (const float*)d_in[5];
    const float* bk    = (const float*)d_in[6];
    const float* Wv    = (const float*)d_in[7];
    const float* bv    = (const float*)d_in[8];
    const float* Wo    = (const float*)d_in[9];
    const float* bo    = (const float*)d_in[10];
    float* out = (float*)d_out;

    float *gq, *gk, *gv, *gc;
    cudaGetSymbolAddress((void**)&gq, g_Q);
    cudaGetSymbolAddress((void**)&gk, g_K);
    cudaGetSymbolAddress((void**)&gv, g_V);
    cudaGetSymbolAddress((void**)&gc, g_C);

    static bool attr_done = false;
    if (!attr_done) {
        cudaFuncSetAttribute(flash_tc, cudaFuncAttributeMaxDynamicSharedMemorySize, 65536);
        attr_done = true;
    }

    dim3 gemm_grid(K_D / 128, K_ROWS / 128);   // (8, 64)
    gemm_tc<<<gemm_grid, 256>>>(query, Wq, bq, gq);
    gemm_tc<<<gemm_grid, 256>>>(key,   Wk, bk, gk);
    gemm_tc<<<gemm_grid, 256>>>(value, Wv, bv, gv);

    dim3 attn_grid(K_B * K_H, K_S / 128);      // (64, 16)
    flash_tc<<<attn_grid, 256, 65536>>>(gq, gk, gv, gc);

    gemm_tc<<<gemm_grid, 256>>>(gc, Wo, bo, out);
}

// round 6
// speedup vs baseline: 2.4149x; 2.1846x over previous
#include <cuda_runtime.h>
#include <cuda_fp16.h>

#define K_B 4
#define K_S 2048
#define K_D 1024
#define K_H 16
#define K_DH 64
#define K_ROWS (K_B * K_S)   // 8192

// Scratch (device globals: allocation-free per harness rules)
__device__ float g_Q[K_ROWS * K_D];
__device__ float g_K[K_ROWS * K_D];
__device__ float g_V[K_ROWS * K_D];
__device__ float g_C[K_ROWS * K_D];

// ---------------------------------------------------------------------------
// fp16 mma + ldmatrix helpers
// ---------------------------------------------------------------------------
__device__ __forceinline__ unsigned h2u(__half2 h) {
    return *reinterpret_cast<unsigned*>(&h);
}

__device__ __forceinline__ void mma_f16(float* d, const uint4 a, unsigned b0, unsigned b1) {
    asm volatile(
        "mma.sync.aligned.m16n8k16.row.col.f32.f16.f16.f32 "
        "{%0,%1,%2,%3}, {%4,%5,%6,%7}, {%8,%9}, {%0,%1,%2,%3};\n"
        : "+f"(d[0]), "+f"(d[1]), "+f"(d[2]), "+f"(d[3])
        : "r"(a.x), "r"(a.y), "r"(a.z), "r"(a.w), "r"(b0), "r"(b1));
}

__device__ __forceinline__ void ldsm_x4(uint4& d, unsigned addr) {
    asm volatile("ldmatrix.sync.aligned.m8n8.x4.shared.b16 {%0,%1,%2,%3}, [%4];"
        : "=r"(d.x), "=r"(d.y), "=r"(d.z), "=r"(d.w) : "r"(addr));
}

__device__ __forceinline__ void ldsm_x4_t(uint4& d, unsigned addr) {
    asm volatile("ldmatrix.sync.aligned.m8n8.x4.trans.shared.b16 {%0,%1,%2,%3}, [%4];"
        : "=r"(d.x), "=r"(d.y), "=r"(d.z), "=r"(d.w) : "r"(addr));
}

// m16n8k16 fp16 fragment maps (r=lane>>2, t=lane&3):
// A: a0=(r,2t..2t+1) a1=(r+8,2t..) a2=(r,8+2t..) a3=(r+8,8+2t..)
// B: b0=(k=2t..2t+1, n=r) b1=(k=8+2t.., n=r)
// C: rows r, r+8; cols 2t, 2t+1  (f32)

// ---------------------------------------------------------------------------
// GEMM: out = x @ W^T + bias. M=8192, N=1024, K=1024.
// BM=BN=128, BK=32, 256 threads (8 warps), warp tile 32x64.
// x,W staged to half in natural row-major smem (padded stride), ldmatrix loads.
// ---------------------------------------------------------------------------
#define SA 40   // half stride (32 data + 8 pad) => 80B rows, ldmatrix conflict-free

__global__ __launch_bounds__(256) void gemm_tc(
    const float* __restrict__ x, const float* __restrict__ W,
    const float* __restrict__ bias, float* __restrict__ out)
{
    __shared__ __half As[128 * SA];   // [m][k] row-major, 10240B
    __shared__ __half Bs[128 * SA];   // [n][k] row-major, 10240B

    const int tid  = threadIdx.x;
    const int lane = tid & 31;
    const int warp = tid >> 5;
    const int wm = warp >> 1;   // 0..3 (32 m-rows each)
    const int wn = warp & 1;    // 0..1 (64 n-cols each)
    const int rowBase = blockIdx.y * 128;
    const int colBase = blockIdx.x * 128;

    const unsigned as_base = (unsigned)__cvta_generic_to_shared(As);
    const unsigned bs_base = (unsigned)__cvta_generic_to_shared(Bs);
    const int u = lane >> 3, j = lane & 7;
    // A-frag unit address components: row = mbase + (u&1)*8 + j, kbyte += (u>>1)*16
    const int a_row = wm * 32 + (u & 1) * 8 + j;
    const int a_kx  = (u >> 1) * 16;
    // B-frag unit: row(n) = nbase + (u>>1)*8 + j, kbyte += (u&1)*16
    const int b_row = wn * 64 + (u >> 1) * 8 + j;
    const int b_kx  = (u & 1) * 16;

    float acc[2][8][4];
    #pragma unroll
    for (int mi = 0; mi < 2; mi++)
        #pragma unroll
        for (int ni = 0; ni < 8; ni++)
            #pragma unroll
            for (int v = 0; v < 4; v++) acc[mi][ni][v] = 0.f;

    float4 pa[4], pb[4];
    #pragma unroll
    for (int i = 0; i < 4; i++) {
        int li = tid + i * 256;
        int m = li >> 3;
        int k = (li & 7) * 4;
        pa[i] = *(const float4*)&x[(size_t)(rowBase + m) * K_D + k];
        pb[i] = *(const float4*)&W[(size_t)(colBase + m) * K_D + k];
    }

    for (int k0 = 0; k0 < K_D; k0 += 32) {
        __syncthreads();   // previous compute done before overwrite
        #pragma unroll
        for (int i = 0; i < 4; i++) {
            int li = tid + i * 256;
            int m = li >> 3;
            int k = (li & 7) * 4;
            uint2 wa, wb;
            wa.x = h2u(__floats2half2_rn(pa[i].x, pa[i].y));
            wa.y = h2u(__floats2half2_rn(pa[i].z, pa[i].w));
            wb.x = h2u(__floats2half2_rn(pb[i].x, pb[i].y));
            wb.y = h2u(__floats2half2_rn(pb[i].z, pb[i].w));
            *(uint2*)&As[m * SA + k] = wa;
            *(uint2*)&Bs[m * SA + k] = wb;
        }
        __syncthreads();

        if (k0 + 32 < K_D) {
            #pragma unroll
            for (int i = 0; i < 4; i++) {
                int li = tid + i * 256;
                int m = li >> 3;
                int k = (li & 7) * 4;
                pa[i] = *(const float4*)&x[(size_t)(rowBase + m) * K_D + k0 + 32 + k];
                pb[i] = *(const float4*)&W[(size_t)(colBase + m) * K_D + k0 + 32 + k];
            }
        }

        #pragma unroll
        for (int kt = 0; kt < 2; kt++) {
            uint4 afr[2];
            #pragma unroll
            for (int mi = 0; mi < 2; mi++)
                ldsm_x4(afr[mi], as_base + (unsigned)((a_row + mi * 16) * (SA * 2) + kt * 32 + a_kx));
            #pragma unroll
            for (int np = 0; np < 4; np++) {
                uint4 bb;
                ldsm_x4(bb, bs_base + (unsigned)((b_row + np * 16) * (SA * 2) + kt * 32 + b_kx));
                #pragma unroll
                for (int mi = 0; mi < 2; mi++) {
                    mma_f16(acc[mi][2 * np],     afr[mi], bb.x, bb.y);
                    mma_f16(acc[mi][2 * np + 1], afr[mi], bb.z, bb.w);
                }
            }
        }
    }

    #pragma unroll
    for (int mi = 0; mi < 2; mi++) {
        int row0 = rowBase + (wm * 2 + mi) * 16 + (lane >> 2);
        #pragma unroll
        for (int ni = 0; ni < 8; ni++) {
            int col = colBase + (wn * 8 + ni) * 8 + (lane & 3) * 2;
            float b0 = __ldg(&bias[col]);
            float b1 = __ldg(&bias[col + 1]);
            float2 v0 = make_float2(acc[mi][ni][0] + b0, acc[mi][ni][1] + b1);
            float2 v1 = make_float2(acc[mi][ni][2] + b0, acc[mi][ni][3] + b1);
            *(float2*)&out[(size_t)row0 * K_D + col] = v0;
            *(float2*)&out[(size_t)(row0 + 8) * K_D + col] = v1;
        }
    }
}

// ---------------------------------------------------------------------------
// Flash attention, fp16 mma (f32 accum/softmax), ldmatrix, P in registers.
// Grid: (B*H, S/128). Block: 256 threads (8 warps), 16 q-rows per warp.
// Bc=32, double-buffered K/V. Dynamic smem 36864B => 2 CTAs/SM.
// ---------------------------------------------------------------------------
#define FS 72   // half stride (64 data + 8 pad) => 144B rows, ldmatrix conflict-free

extern __shared__ __half smem_h[];

__global__ __launch_bounds__(256, 2) void flash_tc(
    const float* __restrict__ Q, const float* __restrict__ K,
    const float* __restrict__ V, float* __restrict__ O)
{
    __half* Qs = smem_h;                       // 128*FS = 9216 half
    __half* KsB[2] = { smem_h + 9216,  smem_h + 9216 + 2304 };   // 32*FS each
    __half* VsB[2] = { smem_h + 13824, smem_h + 13824 + 2304 };

    const int tid  = threadIdx.x;
    const int lane = tid & 31;
    const int warp = tid >> 5;

    const int bh = blockIdx.x;
    const int b = bh / K_H, h = bh % K_H;
    const int qbase = blockIdx.y * 128;
    const size_t base = (size_t)b * K_S * K_D + (size_t)h * K_DH;
    const float scale = 0.125f;   // 1/sqrt(64), exact power of 2

    const int u = lane >> 3, j = lane & 7;
    // Q A-frag: row = warp*16 + (u&1)*8 + j ; kbyte += (u>>1)*16
    const int q_row = warp * 16 + (u & 1) * 8 + j;
    const int q_kx  = (u >> 1) * 16;
    // K B-frag: row(kv) = np*16 + (u>>1)*8 + j ; kbyte += (u&1)*16
    const int k_row = (u >> 1) * 8 + j;
    const int k_kx  = (u & 1) * 16;
    // V B-frag (trans): row(kv) = kt*16 + (u&1)*8 + j ; dimbyte = np*32 + (u>>1)*16
    const int v_row = (u & 1) * 8 + j;
    const int v_dx  = (u >> 1) * 16;

    const unsigned qs_base = (unsigned)__cvta_generic_to_shared(Qs);
    const unsigned ks_base[2] = { (unsigned)__cvta_generic_to_shared(KsB[0]),
                                  (unsigned)__cvta_generic_to_shared(KsB[1]) };
    const unsigned vs_base[2] = { (unsigned)__cvta_generic_to_shared(VsB[0]),
                                  (unsigned)__cvta_generic_to_shared(VsB[1]) };

    // Load Q tile (128x64) -> half, pre-scaled, natural row-major
    #pragma unroll
    for (int i = 0; i < 8; i++) {
        int li = tid + i * 256;
        int m = li >> 4;
        int k = (li & 15) * 4;
        float4 v = *(const float4*)&Q[base + (size_t)(qbase + m) * K_D + k];
        uint2 w;
        w.x = h2u(__floats2half2_rn(v.x * scale, v.y * scale));
        w.y = h2u(__floats2half2_rn(v.z * scale, v.w * scale));
        *(uint2*)&Qs[m * FS + k] = w;
    }

    float accO[8][4];
    #pragma unroll
    for (int ni = 0; ni < 8; ni++)
        #pragma unroll
        for (int v = 0; v < 4; v++) accO[ni][v] = 0.f;

    float m0 = -1e30f, m1 = -1e30f, l0 = 0.f, l1 = 0.f;

    // Prefetch first K/V tile: 32 rows x 64 dims -> 2 float4/thread/tensor
    float4 kpre[2], vpre[2];
    #pragma unroll
    for (int i = 0; i < 2; i++) {
        int li = tid + i * 256;
        int n = li >> 4;
        int k = (li & 15) * 4;
        kpre[i] = *(const float4*)&K[base + (size_t)n * K_D + k];
        vpre[i] = *(const float4*)&V[base + (size_t)n * K_D + k];
    }
    __syncthreads();   // Qs visible

    for (int jt = 0; jt < K_S; jt += 32) {
        const int buf = (jt >> 5) & 1;
        __half* Ks = KsB[buf];
        __half* Vs = VsB[buf];

        // Stage K/V tile (32x64) as half, natural row-major
        #pragma unroll
        for (int i = 0; i < 2; i++) {
            int li = tid + i * 256;
            int n = li >> 4;
            int k = (li & 15) * 4;
            uint2 wk, wv;
            wk.x = h2u(__floats2half2_rn(kpre[i].x, kpre[i].y));
            wk.y = h2u(__floats2half2_rn(kpre[i].z, kpre[i].w));
            wv.x = h2u(__floats2half2_rn(vpre[i].x, vpre[i].y));
            wv.y = h2u(__floats2half2_rn(vpre[i].z, vpre[i].w));
            *(uint2*)&Ks[n * FS + k] = wk;
            *(uint2*)&Vs[n * FS + k] = wv;
        }
        __syncthreads();

        if (jt + 32 < K_S) {
            #pragma unroll
            for (int i = 0; i < 2; i++) {
                int li = tid + i * 256;
                int n = li >> 4;
                int k = (li & 15) * 4;
                kpre[i] = *(const float4*)&K[base + (size_t)(jt + 32 + n) * K_D + k];
                vpre[i] = *(const float4*)&V[base + (size_t)(jt + 32 + n) * K_D + k];
            }
        }

        // ---- S = (Q*scale) K^T : warp tile 16q x 32kv ----
        float accS[4][4];
        #pragma unroll
        for (int ni = 0; ni < 4; ni++)
            #pragma unroll
            for (int v = 0; v < 4; v++) accS[ni][v] = 0.f;

        #pragma unroll
        for (int kt = 0; kt < 4; kt++) {
            uint4 a;
            ldsm_x4(a, qs_base + (unsigned)(q_row * (FS * 2) + kt * 32 + q_kx));
            #pragma unroll
            for (int np = 0; np < 2; np++) {
                uint4 bb;
                ldsm_x4(bb, ks_base[buf] + (unsigned)((k_row + np * 16) * (FS * 2) + kt * 32 + k_kx));
                mma_f16(accS[2 * np],     a, bb.x, bb.y);
                mma_f16(accS[2 * np + 1], a, bb.z, bb.w);
            }
        }

        // ---- online softmax (rows lane>>2 and +8, quad-local) ----
        float mx0 = -1e30f, mx1 = -1e30f;
        #pragma unroll
        for (int ni = 0; ni < 4; ni++) {
            mx0 = fmaxf(mx0, fmaxf(accS[ni][0], accS[ni][1]));
            mx1 = fmaxf(mx1, fmaxf(accS[ni][2], accS[ni][3]));
        }
        mx0 = fmaxf(mx0, __shfl_xor_sync(0xffffffffu, mx0, 1));
        mx0 = fmaxf(mx0, __shfl_xor_sync(0xffffffffu, mx0, 2));
        mx1 = fmaxf(mx1, __shfl_xor_sync(0xffffffffu, mx1, 1));
        mx1 = fmaxf(mx1, __shfl_xor_sync(0xffffffffu, mx1, 2));

        float mn0 = fmaxf(m0, mx0);
        float mn1 = fmaxf(m1, mx1);
        float alpha0 = __expf(m0 - mn0);
        float alpha1 = __expf(m1 - mn1);
        m0 = mn0; m1 = mn1;

        float sum0 = 0.f, sum1 = 0.f;
        #pragma unroll
        for (int ni = 0; ni < 4; ni++) {
            accS[ni][0] = __expf(accS[ni][0] - mn0);
            accS[ni][1] = __expf(accS[ni][1] - mn0);
            accS[ni][2] = __expf(accS[ni][2] - mn1);
            accS[ni][3] = __expf(accS[ni][3] - mn1);
            sum0 += accS[ni][0] + accS[ni][1];
            sum1 += accS[ni][2] + accS[ni][3];
        }
        sum0 += __shfl_xor_sync(0xffffffffu, sum0, 1);
        sum0 += __shfl_xor_sync(0xffffffffu, sum0, 2);
        sum1 += __shfl_xor_sync(0xffffffffu, sum1, 1);
        sum1 += __shfl_xor_sync(0xffffffffu, sum1, 2);
        l0 = l0 * alpha0 + sum0;
        l1 = l1 * alpha1 + sum1;

        #pragma unroll
        for (int ni = 0; ni < 8; ni++) {
            accO[ni][0] *= alpha0; accO[ni][1] *= alpha0;
            accO[ni][2] *= alpha1; accO[ni][3] *= alpha1;
        }

        // ---- O += P @ V : P C-frag f32 pairs -> fp16 A-frag regs directly ----
        #pragma unroll
        for (int kt = 0; kt < 2; kt++) {
            uint4 aP;
            aP.x = h2u(__floats2half2_rn(accS[2 * kt][0],     accS[2 * kt][1]));      // (r,   k 2t..)
            aP.y = h2u(__floats2half2_rn(accS[2 * kt][2],     accS[2 * kt][3]));      // (r+8, k 2t..)
            aP.z = h2u(__floats2half2_rn(accS[2 * kt + 1][0], accS[2 * kt + 1][1]));  // (r,   k 8+2t..)
            aP.w = h2u(__floats2half2_rn(accS[2 * kt + 1][2], accS[2 * kt + 1][3]));  // (r+8, k 8+2t..)
            #pragma unroll
            for (int np = 0; np < 4; np++) {
                uint4 bb;
                ldsm_x4_t(bb, vs_base[buf] + (unsigned)((kt * 16 + v_row) * (FS * 2) + np * 32 + v_dx));
                mma_f16(accO[2 * np],     aP, bb.x, bb.y);
                mma_f16(accO[2 * np + 1], aP, bb.z, bb.w);
            }
        }
    }

    // Epilogue: normalize and write context
    float inv0 = 1.0f / l0;
    float inv1 = 1.0f / l1;
    int row0 = qbase + warp * 16 + (lane >> 2);
    #pragma unroll
    for (int ni = 0; ni < 8; ni++) {
        int col = ni * 8 + (lane & 3) * 2;
        float2 v0 = make_float2(accO[ni][0] * inv0, accO[ni][1] * inv0);
        float2 v1 = make_float2(accO[ni][2] * inv1, accO[ni][3] * inv1);
        *(float2*)&O[base + (size_t)row0 * K_D + col] = v0;
        *(float2*)&O[base + (size_t)(row0 + 8) * K_D + col] = v1;
    }
}

// ---------------------------------------------------------------------------
extern "C" void kernel_launch(void* const* d_in, const int* in_sizes, int n_in,
                              void* d_out, int out_size)
{
    const float* query = (const float*)d_in[0];
    const float* key   = (const float*)d_in[1];
    const float* value = (const float*)d_in[2];
    const float* Wq    = (const float*)d_in[3];
    const float* bq    = (const float*)d_in[4];
    const float* Wk    = (const float*)d_in[5];
    const float* bk    = (const float*)d_in[6];
    const float* Wv    = (const float*)d_in[7];
    const float* bv    = (const float*)d_in[8];
    const float* Wo    = (const float*)d_in[9];
    const float* bo    = (const float*)d_in[10];
    float* out = (float*)d_out;

    float *gq, *gk, *gv, *gc;
    cudaGetSymbolAddress((void**)&gq, g_Q);
    cudaGetSymbolAddress((void**)&gk, g_K);
    cudaGetSymbolAddress((void**)&gv, g_V);
    cudaGetSymbolAddress((void**)&gc, g_C);

    dim3 gemm_grid(K_D / 128, K_ROWS / 128);   // (8, 64)
    gemm_tc<<<gemm_grid, 256>>>(query, Wq, bq, gq);
    gemm_tc<<<gemm_grid, 256>>>(key,   Wk, bk, gk);
    gemm_tc<<<gemm_grid, 256>>>(value, Wv, bv, gv);

    dim3 attn_grid(K_B * K_H, K_S / 128);      // (64, 16)
    flash_tc<<<attn_grid, 256, 36864>>>(gq, gk, gv, gc);

    gemm_tc<<<gemm_grid, 256>>>(gc, Wo, bo, out);
}

// round 7
// speedup vs baseline: 3.2947x; 1.3643x over previous
#include <cuda_runtime.h>
#include <cuda_fp16.h>

#define K_B 4
#define K_S 2048
#define K_D 1024
#define K_H 16
#define K_DH 64
#define K_ROWS (K_B * K_S)   // 8192

// Half-precision scratch (device globals: allocation-free per harness rules)
__device__ __half g_Xq[K_ROWS * K_D];   // query  -> half
__device__ __half g_Xk[K_ROWS * K_D];   // key    -> half
__device__ __half g_Xv[K_ROWS * K_D];   // value  -> half
__device__ __half g_hWq[K_D * K_D];
__device__ __half g_hWk[K_D * K_D];
__device__ __half g_hWv[K_D * K_D];
__device__ __half g_hWo[K_D * K_D];
__device__ __half g_Qh[K_ROWS * K_D];
__device__ __half g_Kh[K_ROWS * K_D];
__device__ __half g_Vh[K_ROWS * K_D];
__device__ __half g_Ch[K_ROWS * K_D];

// ---------------------------------------------------------------------------
// helpers
// ---------------------------------------------------------------------------
__device__ __forceinline__ unsigned h2u(__half2 h) {
    return *reinterpret_cast<unsigned*>(&h);
}

__device__ __forceinline__ float ex2f(float x) {
    float y;
    asm("ex2.approx.f32 %0, %1;" : "=f"(y) : "f"(x));
    return y;
}

__device__ __forceinline__ void mma_f16(float* d, const uint4 a, unsigned b0, unsigned b1) {
    asm volatile(
        "mma.sync.aligned.m16n8k16.row.col.f32.f16.f16.f32 "
        "{%0,%1,%2,%3}, {%4,%5,%6,%7}, {%8,%9}, {%0,%1,%2,%3};\n"
        : "+f"(d[0]), "+f"(d[1]), "+f"(d[2]), "+f"(d[3])
        : "r"(a.x), "r"(a.y), "r"(a.z), "r"(a.w), "r"(b0), "r"(b1));
}

__device__ __forceinline__ void ldsm_x4(uint4& d, unsigned addr) {
    asm volatile("ldmatrix.sync.aligned.m8n8.x4.shared.b16 {%0,%1,%2,%3}, [%4];"
        : "=r"(d.x), "=r"(d.y), "=r"(d.z), "=r"(d.w) : "r"(addr));
}

__device__ __forceinline__ void ldsm_x4_t(uint4& d, unsigned addr) {
    asm volatile("ldmatrix.sync.aligned.m8n8.x4.trans.shared.b16 {%0,%1,%2,%3}, [%4];"
        : "=r"(d.x), "=r"(d.y), "=r"(d.z), "=r"(d.w) : "r"(addr));
}

__device__ __forceinline__ void cp16(unsigned dst, const void* src) {
    asm volatile("cp.async.cg.shared.global [%0], [%1], 16;\n" :: "r"(dst), "l"(src));
}
#define CP_COMMIT() asm volatile("cp.async.commit_group;\n" ::: "memory")
#define CP_WAIT0()  asm volatile("cp.async.wait_group 0;\n" ::: "memory")

// ---------------------------------------------------------------------------
// Conversion kernel: f32 -> f16 for 3 activations + 4 weight matrices
// ---------------------------------------------------------------------------
__global__ __launch_bounds__(256) void cvt_all(
    const float* s0, const float* s1, const float* s2, const float* s3,
    const float* s4, const float* s5, const float* s6,
    __half* d0, __half* d1, __half* d2, __half* d3,
    __half* d4, __half* d5, __half* d6)
{
    const float* ss[7] = {s0, s1, s2, s3, s4, s5, s6};
    __half* dd[7] = {d0, d1, d2, d3, d4, d5, d6};
    int t = blockIdx.y;
    int n4 = (t < 3) ? (K_ROWS * K_D / 4) : (K_D * K_D / 4);
    const float4* src = (const float4*)ss[t];
    uint2* dst = (uint2*)dd[t];
    for (int i = blockIdx.x * 256 + threadIdx.x; i < n4; i += gridDim.x * 256) {
        float4 v = src[i];
        uint2 w;
        w.x = h2u(__floats2half2_rn(v.x, v.y));
        w.y = h2u(__floats2half2_rn(v.z, v.w));
        dst[i] = w;
    }
}

// ---------------------------------------------------------------------------
// GEMM: out = x @ W^T + bias (x, W in half; out half or float).
// BM=BN=128, BK=32, 256 threads (8 warps), warp tile 32x64.
// cp.async double-buffered staging, ldmatrix fragment loads.
// ---------------------------------------------------------------------------
#define SA 40                   // half stride: 32 data + 8 pad => 80B rows
#define GT_BYTES (128 * SA * 2) // 10240 bytes per tile buffer

template <typename OutT>
__global__ __launch_bounds__(256) void gemm_tc(
    const __half* __restrict__ x, const __half* __restrict__ W,
    const float* __restrict__ bias, OutT* __restrict__ out)
{
    __shared__ __half As[2][128 * SA];
    __shared__ __half Bs[2][128 * SA];

    const int tid  = threadIdx.x;
    const int lane = tid & 31;
    const int warp = tid >> 5;
    const int wm = warp >> 1;   // 0..3 (32 m-rows each)
    const int wn = warp & 1;    // 0..1 (64 n-cols each)
    const int rowBase = blockIdx.y * 128;
    const int colBase = blockIdx.x * 128;

    const unsigned as_base = (unsigned)__cvta_generic_to_shared(As);
    const unsigned bs_base = (unsigned)__cvta_generic_to_shared(Bs);
    const int u = lane >> 3, j = lane & 7;
    const int a_row = wm * 32 + (u & 1) * 8 + j;
    const int a_kx  = (u >> 1) * 16;
    const int b_row = wn * 64 + (u >> 1) * 8 + j;
    const int b_kx  = (u & 1) * 16;

    // staging map: 512 16B chunks per matrix (128 rows x 4 chunks), 2/thread
    const int sc0 = tid * 2;
    const int sr0 = sc0 >> 2, sh0 = (sc0 & 3);

    float acc[2][8][4];
    #pragma unroll
    for (int mi = 0; mi < 2; mi++)
        #pragma unroll
        for (int ni = 0; ni < 8; ni++)
            #pragma unroll
            for (int v = 0; v < 4; v++) acc[mi][ni][v] = 0.f;

    // prologue: stage k0=0 into buf 0
    #pragma unroll
    for (int i = 0; i < 2; i++) {
        int r = sr0, ch = sh0 + i;
        cp16(as_base + (unsigned)(r * 80 + ch * 16),
             x + (size_t)(rowBase + r) * K_D + ch * 8);
        cp16(bs_base + (unsigned)(r * 80 + ch * 16),
             W + (size_t)(colBase + r) * K_D + ch * 8);
    }
    CP_COMMIT();
    CP_WAIT0();
    __syncthreads();

    for (int k0 = 0; k0 < K_D; k0 += 32) {
        const int buf = (k0 >> 5) & 1;
        // issue next tile into other buffer
        if (k0 + 32 < K_D) {
            const unsigned off = (unsigned)((buf ^ 1) * GT_BYTES);
            #pragma unroll
            for (int i = 0; i < 2; i++) {
                int r = sr0, ch = sh0 + i;
                cp16(as_base + off + (unsigned)(r * 80 + ch * 16),
                     x + (size_t)(rowBase + r) * K_D + k0 + 32 + ch * 8);
                cp16(bs_base + off + (unsigned)(r * 80 + ch * 16),
                     W + (size_t)(colBase + r) * K_D + k0 + 32 + ch * 8);
            }
        }
        CP_COMMIT();

        const unsigned ab = as_base + (unsigned)(buf * GT_BYTES);
        const unsigned bb_ = bs_base + (unsigned)(buf * GT_BYTES);
        #pragma unroll
        for (int kt = 0; kt < 2; kt++) {
            uint4 afr[2];
            #pragma unroll
            for (int mi = 0; mi < 2; mi++)
                ldsm_x4(afr[mi], ab + (unsigned)((a_row + mi * 16) * 80 + kt * 32 + a_kx));
            #pragma unroll
            for (int np = 0; np < 4; np++) {
                uint4 bb;
                ldsm_x4(bb, bb_ + (unsigned)((b_row + np * 16) * 80 + kt * 32 + b_kx));
                #pragma unroll
                for (int mi = 0; mi < 2; mi++) {
                    mma_f16(acc[mi][2 * np],     afr[mi], bb.x, bb.y);
                    mma_f16(acc[mi][2 * np + 1], afr[mi], bb.z, bb.w);
                }
            }
        }
        CP_WAIT0();
        __syncthreads();
    }

    #pragma unroll
    for (int mi = 0; mi < 2; mi++) {
        int row0 = rowBase + (wm * 2 + mi) * 16 + (lane >> 2);
        #pragma unroll
        for (int ni = 0; ni < 8; ni++) {
            int col = colBase + (wn * 8 + ni) * 8 + (lane & 3) * 2;
            float b0 = __ldg(&bias[col]);
            float b1 = __ldg(&bias[col + 1]);
            float c00 = acc[mi][ni][0] + b0, c01 = acc[mi][ni][1] + b1;
            float c10 = acc[mi][ni][2] + b0, c11 = acc[mi][ni][3] + b1;
            if constexpr (sizeof(OutT) == 2) {
                *(__half2*)&out[(size_t)row0 * K_D + col] = __floats2half2_rn(c00, c01);
                *(__half2*)&out[(size_t)(row0 + 8) * K_D + col] = __floats2half2_rn(c10, c11);
            } else {
                *(float2*)&out[(size_t)row0 * K_D + col] = make_float2(c00, c01);
                *(float2*)&out[(size_t)(row0 + 8) * K_D + col] = make_float2(c10, c11);
            }
        }
    }
}

// ---------------------------------------------------------------------------
// Flash attention, fp16 in/out, cp.async staging, exp2 softmax.
// Grid: (B*H, S/128). Block: 256 threads (8 warps), 16 q-rows per warp.
// Bc=32, double-buffered K/V. Dynamic smem 36864B => 2 CTAs/SM.
// ---------------------------------------------------------------------------
#define FS 72   // half stride (64 data + 8 pad) => 144B rows

extern __shared__ __half smem_h[];

__global__ __launch_bounds__(256, 2) void flash_tc(
    const __half* __restrict__ Q, const __half* __restrict__ K,
    const __half* __restrict__ V, __half* __restrict__ O)
{
    // Qs: 128*FS = 9216 halves; K/V buffers: 32*FS = 2304 halves each
    const unsigned qs_base = (unsigned)__cvta_generic_to_shared(smem_h);
    const unsigned ks_base[2] = { qs_base + 9216 * 2,  qs_base + 11520 * 2 };
    const unsigned vs_base[2] = { qs_base + 13824 * 2, qs_base + 16128 * 2 };

    const int tid  = threadIdx.x;
    const int lane = tid & 31;
    const int warp = tid >> 5;

    const int bh = blockIdx.x;
    const int b = bh / K_H, h = bh % K_H;
    const int qbase = blockIdx.y * 128;
    const size_t base = (size_t)b * K_S * K_D + (size_t)h * K_DH;
    const float cl2 = 0.18033688f;   // (1/sqrt(64)) * log2(e)

    const int u = lane >> 3, j = lane & 7;
    const int q_row = warp * 16 + (u & 1) * 8 + j;
    const int q_kx  = (u >> 1) * 16;
    const int k_row = (u >> 1) * 8 + j;
    const int k_kx  = (u & 1) * 16;
    const int v_row = (u & 1) * 8 + j;
    const int v_dx  = (u >> 1) * 16;

    // staging maps
    const int kv_r = tid >> 3, kv_c = tid & 7;   // K/V: 256 chunks, 1/thread

    // prologue: stage Q (1024 chunks, 4/thread) + first K/V tile
    #pragma unroll
    for (int i = 0; i < 4; i++) {
        int c = tid + i * 256;
        int r = c >> 3, ch = c & 7;
        cp16(qs_base + (unsigned)(r * 144 + ch * 16),
             Q + base + (size_t)(qbase + r) * K_D + ch * 8);
    }
    cp16(ks_base[0] + (unsigned)(kv_r * 144 + kv_c * 16),
         K + base + (size_t)kv_r * K_D + kv_c * 8);
    cp16(vs_base[0] + (unsigned)(kv_r * 144 + kv_c * 16),
         V + base + (size_t)kv_r * K_D + kv_c * 8);
    CP_COMMIT();

    float accO[8][4];
    #pragma unroll
    for (int ni = 0; ni < 8; ni++)
        #pragma unroll
        for (int v = 0; v < 4; v++) accO[ni][v] = 0.f;

    float m0 = -1e30f, m1 = -1e30f, l0 = 0.f, l1 = 0.f;

    CP_WAIT0();
    __syncthreads();

    for (int jt = 0; jt < K_S; jt += 32) {
        const int buf = (jt >> 5) & 1;

        // issue next K/V tile into other buffer
        if (jt + 32 < K_S) {
            cp16(ks_base[buf ^ 1] + (unsigned)(kv_r * 144 + kv_c * 16),
                 K + base + (size_t)(jt + 32 + kv_r) * K_D + kv_c * 8);
            cp16(vs_base[buf ^ 1] + (unsigned)(kv_r * 144 + kv_c * 16),
                 V + base + (size_t)(jt + 32 + kv_r) * K_D + kv_c * 8);
        }
        CP_COMMIT();

        // ---- S = Q K^T (raw; scale folded into exp2) ----
        float accS[4][4];
        #pragma unroll
        for (int ni = 0; ni < 4; ni++)
            #pragma unroll
            for (int v = 0; v < 4; v++) accS[ni][v] = 0.f;

        #pragma unroll
        for (int kt = 0; kt < 4; kt++) {
            uint4 a;
            ldsm_x4(a, qs_base + (unsigned)(q_row * 144 + kt * 32 + q_kx));
            #pragma unroll
            for (int np = 0; np < 2; np++) {
                uint4 bb;
                ldsm_x4(bb, ks_base[buf] + (unsigned)((k_row + np * 16) * 144 + kt * 32 + k_kx));
                mma_f16(accS[2 * np],     a, bb.x, bb.y);
                mma_f16(accS[2 * np + 1], a, bb.z, bb.w);
            }
        }

        // ---- online softmax in exp2 domain (rows lane>>2, +8; quad-local) ----
        float mx0 = -1e30f, mx1 = -1e30f;
        #pragma unroll
        for (int ni = 0; ni < 4; ni++) {
            mx0 = fmaxf(mx0, fmaxf(accS[ni][0], accS[ni][1]));
            mx1 = fmaxf(mx1, fmaxf(accS[ni][2], accS[ni][3]));
        }
        mx0 = fmaxf(mx0, __shfl_xor_sync(0xffffffffu, mx0, 1));
        mx0 = fmaxf(mx0, __shfl_xor_sync(0xffffffffu, mx0, 2));
        mx1 = fmaxf(mx1, __shfl_xor_sync(0xffffffffu, mx1, 1));
        mx1 = fmaxf(mx1, __shfl_xor_sync(0xffffffffu, mx1, 2));

        float mn0 = fmaxf(m0, mx0);
        float mn1 = fmaxf(m1, mx1);
        float alpha0 = ex2f((m0 - mn0) * cl2);
        float alpha1 = ex2f((m1 - mn1) * cl2);
        m0 = mn0; m1 = mn1;
        float mc0 = mn0 * cl2, mc1 = mn1 * cl2;

        float sum0 = 0.f, sum1 = 0.f;
        #pragma unroll
        for (int ni = 0; ni < 4; ni++) {
            accS[ni][0] = ex2f(fmaf(accS[ni][0], cl2, -mc0));
            accS[ni][1] = ex2f(fmaf(accS[ni][1], cl2, -mc0));
            accS[ni][2] = ex2f(fmaf(accS[ni][2], cl2, -mc1));
            accS[ni][3] = ex2f(fmaf(accS[ni][3], cl2, -mc1));
            sum0 += accS[ni][0] + accS[ni][1];
            sum1 += accS[ni][2] + accS[ni][3];
        }
        sum0 += __shfl_xor_sync(0xffffffffu, sum0, 1);
        sum0 += __shfl_xor_sync(0xffffffffu, sum0, 2);
        sum1 += __shfl_xor_sync(0xffffffffu, sum1, 1);
        sum1 += __shfl_xor_sync(0xffffffffu, sum1, 2);
        l0 = l0 * alpha0 + sum0;
        l1 = l1 * alpha1 + sum1;

        #pragma unroll
        for (int ni = 0; ni < 8; ni++) {
            accO[ni][0] *= alpha0; accO[ni][1] *= alpha0;
            accO[ni][2] *= alpha1; accO[ni][3] *= alpha1;
        }

        // ---- O += P @ V : P C-frag f32 pairs -> fp16 A-frag regs directly ----
        #pragma unroll
        for (int kt = 0; kt < 2; kt++) {
            uint4 aP;
            aP.x = h2u(__floats2half2_rn(accS[2 * kt][0],     accS[2 * kt][1]));
            aP.y = h2u(__floats2half2_rn(accS[2 * kt][2],     accS[2 * kt][3]));
            aP.z = h2u(__floats2half2_rn(accS[2 * kt + 1][0], accS[2 * kt + 1][1]));
            aP.w = h2u(__floats2half2_rn(accS[2 * kt + 1][2], accS[2 * kt + 1][3]));
            #pragma unroll
            for (int np = 0; np < 4; np++) {
                uint4 bb;
                ldsm_x4_t(bb, vs_base[buf] + (unsigned)((kt * 16 + v_row) * 144 + np * 32 + v_dx));
                mma_f16(accO[2 * np],     aP, bb.x, bb.y);
                mma_f16(accO[2 * np + 1], aP, bb.z, bb.w);
            }
        }

        CP_WAIT0();
        __syncthreads();
    }

    // Epilogue: normalize and write half context
    float inv0 = 1.0f / l0;
    float inv1 = 1.0f / l1;
    int row0 = qbase + warp * 16 + (lane >> 2);
    #pragma unroll
    for (int ni = 0; ni < 8; ni++) {
        int col = ni * 8 + (lane & 3) * 2;
        *(__half2*)&O[base + (size_t)row0 * K_D + col] =
            __floats2half2_rn(accO[ni][0] * inv0, accO[ni][1] * inv0);
        *(__half2*)&O[base + (size_t)(row0 + 8) * K_D + col] =
            __floats2half2_rn(accO[ni][2] * inv1, accO[ni][3] * inv1);
    }
}

// ---------------------------------------------------------------------------
extern "C" void kernel_launch(void* const* d_in, const int* in_sizes, int n_in,
                              void* d_out, int out_size)
{
    const float* query = (const float*)d_in[0];
    const float* key   = (const float*)d_in[1];
    const float* value = (const float*)d_in[2];
    const float* Wq    = (const float*)d_in[3];
    const float* bq    = (const float*)d_in[4];
    const float* Wk    = (const float*)d_in[5];
    const float* bk    = (const float*)d_in[6];
    const float* Wv    = (const float*)d_in[7];
    const float* bv    = (const float*)d_in[8];
    const float* Wo    = (const float*)d_in[9];
    const float* bo    = (const float*)d_in[10];
    float* out = (float*)d_out;

    __half *xq, *xk, *xv, *hwq, *hwk, *hwv, *hwo, *qh, *kh, *vh, *ch;
    cudaGetSymbolAddress((void**)&xq, g_Xq);
    cudaGetSymbolAddress((void**)&xk, g_Xk);
    cudaGetSymbolAddress((void**)&xv, g_Xv);
    cudaGetSymbolAddress((void**)&hwq, g_hWq);
    cudaGetSymbolAddress((void**)&hwk, g_hWk);
    cudaGetSymbolAddress((void**)&hwv, g_hWv);
    cudaGetSymbolAddress((void**)&hwo, g_hWo);
    cudaGetSymbolAddress((void**)&qh, g_Qh);
    cudaGetSymbolAddress((void**)&kh, g_Kh);
    cudaGetSymbolAddress((void**)&vh, g_Vh);
    cudaGetSymbolAddress((void**)&ch, g_Ch);

    // 1) convert inputs + weights to half
    dim3 cvt_grid(512, 7);
    cvt_all<<<cvt_grid, 256>>>(query, key, value, Wq, Wk, Wv, Wo,
                               xq, xk, xv, hwq, hwk, hwv, hwo);

    // 2) projections (half in, half out)
    dim3 gemm_grid(K_D / 128, K_ROWS / 128);   // (8, 64)
    gemm_tc<__half><<<gemm_grid, 256>>>(xq, hwq, bq, qh);
    gemm_tc<__half><<<gemm_grid, 256>>>(xk, hwk, bk, kh);
    gemm_tc<__half><<<gemm_grid, 256>>>(xv, hwv, bv, vh);

    // 3) attention (half in, half out)
    dim3 attn_grid(K_B * K_H, K_S / 128);      // (64, 16)
    flash_tc<<<attn_grid, 256, 36864>>>(qh, kh, vh, ch);

    // 4) output projection (half in, float out)
    gemm_tc<float><<<gemm_grid, 256>>>(ch, hwo, bo, out);
}

// round 10
// speedup vs baseline: 3.8927x; 1.1815x over previous
#include <cuda_runtime.h>
#include <cuda_fp16.h>
#include <cstdint>

#define K_B 4
#define K_S 2048
#define K_D 1024
#define K_H 16
#define K_DH 64
#define K_ROWS (K_B * K_S)   // 8192

// Half-precision scratch (device globals: allocation-free per harness rules)
__device__ __half g_Xq[K_ROWS * K_D];
__device__ __half g_Xk[K_ROWS * K_D];
__device__ __half g_Xv[K_ROWS * K_D];
__device__ __half g_hWq[K_D * K_D];
__device__ __half g_hWk[K_D * K_D];
__device__ __half g_hWv[K_D * K_D];
__device__ __half g_hWo[K_D * K_D];
__device__ __half g_Qh[K_ROWS * K_D];
__device__ __half g_Kh[K_ROWS * K_D];
__device__ __half g_Vh[K_ROWS * K_D];
__device__ __half g_Ch[K_ROWS * K_D];

// ---------------------------------------------------------------------------
// helpers
// ---------------------------------------------------------------------------
__device__ __forceinline__ unsigned h2u(__half2 h) {
    return *reinterpret_cast<unsigned*>(&h);
}

__device__ __forceinline__ float ex2f(float x) {
    float y;
    asm("ex2.approx.f32 %0, %1;" : "=f"(y) : "f"(x));
    return y;
}

__device__ __forceinline__ void mma_f16(float* d, const uint4 a, unsigned b0, unsigned b1) {
    asm volatile(
        "mma.sync.aligned.m16n8k16.row.col.f32.f16.f16.f32 "
        "{%0,%1,%2,%3}, {%4,%5,%6,%7}, {%8,%9}, {%0,%1,%2,%3};\n"
        : "+f"(d[0]), "+f"(d[1]), "+f"(d[2]), "+f"(d[3])
        : "r"(a.x), "r"(a.y), "r"(a.z), "r"(a.w), "r"(b0), "r"(b1));
}

__device__ __forceinline__ void ldsm_x4(uint4& d, unsigned addr) {
    asm volatile("ldmatrix.sync.aligned.m8n8.x4.shared.b16 {%0,%1,%2,%3}, [%4];"
        : "=r"(d.x), "=r"(d.y), "=r"(d.z), "=r"(d.w) : "r"(addr));
}

__device__ __forceinline__ void ldsm_x4_t(uint4& d, unsigned addr) {
    asm volatile("ldmatrix.sync.aligned.m8n8.x4.trans.shared.b16 {%0,%1,%2,%3}, [%4];"
        : "=r"(d.x), "=r"(d.y), "=r"(d.z), "=r"(d.w) : "r"(addr));
}

__device__ __forceinline__ void cp16(unsigned dst, const void* src) {
    asm volatile("cp.async.cg.shared.global [%0], [%1], 16;\n" :: "r"(dst), "l"(src));
}
#define CP_COMMIT() asm volatile("cp.async.commit_group;\n" ::: "memory")
#define CP_WAIT0()  asm volatile("cp.async.wait_group 0;\n" ::: "memory")
#define CP_WAIT1()  asm volatile("cp.async.wait_group 1;\n" ::: "memory")

// ---------------------------------------------------------------------------
// Conversion kernel: f32 -> f16 for 3 activations + 4 weight matrices
// ---------------------------------------------------------------------------
__global__ __launch_bounds__(256) void cvt_all(
    const float* s0, const float* s1, const float* s2, const float* s3,
    const float* s4, const float* s5, const float* s6,
    __half* d0, __half* d1, __half* d2, __half* d3,
    __half* d4, __half* d5, __half* d6)
{
    const float* ss[7] = {s0, s1, s2, s3, s4, s5, s6};
    __half* dd[7] = {d0, d1, d2, d3, d4, d5, d6};
    int t = blockIdx.y;
    int n4 = (t < 3) ? (K_ROWS * K_D / 4) : (K_D * K_D / 4);
    const float4* src = (const float4*)ss[t];
    uint2* dst = (uint2*)dd[t];
    for (int i = blockIdx.x * 256 + threadIdx.x; i < n4; i += gridDim.x * 256) {
        float4 v = src[i];
        uint2 w;
        w.x = h2u(__floats2half2_rn(v.x, v.y));
        w.y = h2u(__floats2half2_rn(v.z, v.w));
        dst[i] = w;
    }
}

// ---------------------------------------------------------------------------
// GEMM: out = x @ W^T + bias (half in; out half or float).
// BM=BN=128, BK=32, 256 threads (8 warps), warp tile 32x64.
// 3-stage cp.async pipeline, ONE __syncthreads per k-iter.
// Batched over blockIdx.z (3 independent GEMMs) to fill waves.
// Dynamic smem: 3 * (10240 A + 10240 B) = 61440 B. 2 CTAs/SM.
// ---------------------------------------------------------------------------
extern __shared__ unsigned char smem_raw[];

template <typename OutT>
__global__ __launch_bounds__(256, 2) void gemm_tc(
    const __half* __restrict__ x0, const __half* __restrict__ x1, const __half* __restrict__ x2,
    const __half* __restrict__ w0, const __half* __restrict__ w1, const __half* __restrict__ w2,
    const float* __restrict__ b0,  const float* __restrict__ b1,  const float* __restrict__ b2,
    OutT* __restrict__ o0, OutT* __restrict__ o1, OutT* __restrict__ o2)
{
    const int z = blockIdx.z;
    const __half* x = (z == 0) ? x0 : (z == 1) ? x1 : x2;
    const __half* W = (z == 0) ? w0 : (z == 1) ? w1 : w2;
    const float* bias = (z == 0) ? b0 : (z == 1) ? b1 : b2;
    OutT* out = (z == 0) ? o0 : (z == 1) ? o1 : o2;

    const int tid  = threadIdx.x;
    const int lane = tid & 31;
    const int warp = tid >> 5;
    const int wm = warp >> 1;   // 0..3 (32 m-rows each)
    const int wn = warp & 1;    // 0..1 (64 n-cols each)
    const int rowBase = blockIdx.y * 128;
    const int colBase = blockIdx.x * 128;

    const unsigned sb = (unsigned)__cvta_generic_to_shared(smem_raw);
    const int u = lane >> 3, j = lane & 7;
    const int a_row = wm * 32 + (u & 1) * 8 + j;
    const int a_kx  = (u >> 1) * 16;
    const int b_row = wn * 64 + (u >> 1) * 8 + j;
    const int b_kx  = (u & 1) * 16;

    // staging: per matrix 512 chunks (128 rows x 4 x 16B), 2/thread
    auto stage = [&](int t, int s) {
        const unsigned ab = sb + (unsigned)s * 20480u;
        const unsigned bb = ab + 10240u;
        const int k0 = t * 32;
        #pragma unroll
        for (int i = 0; i < 2; i++) {
            int ca = tid + i * 256;        // 0..511
            int r = ca >> 2, c = ca & 3;
            cp16(ab + (unsigned)(r * 80 + c * 16),
                 x + (size_t)(rowBase + r) * K_D + k0 + c * 8);
            cp16(bb + (unsigned)(r * 80 + c * 16),
                 W + (size_t)(colBase + r) * K_D + k0 + c * 8);
        }
        CP_COMMIT();
    };

    float acc[2][8][4];
    #pragma unroll
    for (int mi = 0; mi < 2; mi++)
        #pragma unroll
        for (int ni = 0; ni < 8; ni++)
            #pragma unroll
            for (int v = 0; v < 4; v++) acc[mi][ni][v] = 0.f;

    const int NT = K_D / 32;   // 32 k-tiles
    stage(0, 0);
    stage(1, 1);

    for (int it = 0; it < NT; it++) {
        const int buf = it % 3;
        if (it == NT - 1) { CP_WAIT0(); } else { CP_WAIT1(); }
        __syncthreads();
        if (it + 2 < NT) stage(it + 2, (it + 2) % 3);

        const unsigned ab = sb + (unsigned)buf * 20480u;
        const unsigned bb_ = ab + 10240u;
        #pragma unroll
        for (int kt = 0; kt < 2; kt++) {
            uint4 afr[2];
            #pragma unroll
            for (int mi = 0; mi < 2; mi++)
                ldsm_x4(afr[mi], ab + (unsigned)((a_row + mi * 16) * 80 + kt * 32 + a_kx));
            #pragma unroll
            for (int np = 0; np < 4; np++) {
                uint4 bb;
                ldsm_x4(bb, bb_ + (unsigned)((b_row + np * 16) * 80 + kt * 32 + b_kx));
                #pragma unroll
                for (int mi = 0; mi < 2; mi++) {
                    mma_f16(acc[mi][2 * np],     afr[mi], bb.x, bb.y);
                    mma_f16(acc[mi][2 * np + 1], afr[mi], bb.z, bb.w);
                }
            }
        }
    }

    #pragma unroll
    for (int mi = 0; mi < 2; mi++) {
        int row0 = rowBase + (wm * 2 + mi) * 16 + (lane >> 2);
        #pragma unroll
        for (int ni = 0; ni < 8; ni++) {
            int col = colBase + (wn * 8 + ni) * 8 + (lane & 3) * 2;
            float bb0 = __ldg(&bias[col]);
            float bb1 = __ldg(&bias[col + 1]);
            float c00 = acc[mi][ni][0] + bb0, c01 = acc[mi][ni][1] + bb1;
            float c10 = acc[mi][ni][2] + bb0, c11 = acc[mi][ni][3] + bb1;
            if constexpr (sizeof(OutT) == 2) {
                *(__half2*)&out[(size_t)row0 * K_D + col] = __floats2half2_rn(c00, c01);
                *(__half2*)&out[(size_t)(row0 + 8) * K_D + col] = __floats2half2_rn(c10, c11);
            } else {
                *(float2*)&out[(size_t)row0 * K_D + col] = make_float2(c00, c01);
                *(float2*)&out[(size_t)(row0 + 8) * K_D + col] = make_float2(c10, c11);
            }
        }
    }
}

// ---------------------------------------------------------------------------
// Flash attention: fp16 mma.sync, Bc=64, 3-stage cp.async, exp2 softmax.
// Grid: (B*H, S/128). Block: 256 threads (8 warps), 16 q-rows per warp.
// Dynamic smem: Q 18432 + 3*(K 9216 + V 9216) = 73728 B. 2 CTAs/SM.
// ---------------------------------------------------------------------------
#define FS 72   // half stride (64 data + 8 pad) => 144B rows

__global__ __launch_bounds__(256, 2) void flash_tc(
    const __half* __restrict__ Q, const __half* __restrict__ K,
    const __half* __restrict__ V, __half* __restrict__ O)
{
    const unsigned qs_base = (unsigned)__cvta_generic_to_shared(smem_raw);

    const int tid  = threadIdx.x;
    const int lane = tid & 31;
    const int warp = tid >> 5;

    const int bh = blockIdx.x;
    const int b = bh / K_H, h = bh % K_H;
    const int qbase = blockIdx.y * 128;
    const size_t base = (size_t)b * K_S * K_D + (size_t)h * K_DH;
    const float cl2 = 0.18033688f;   // (1/sqrt(64)) * log2(e)

    const int u = lane >> 3, j = lane & 7;
    const int q_row = warp * 16 + (u & 1) * 8 + j;
    const int q_kx  = (u >> 1) * 16;
    const int k_row = (u >> 1) * 8 + j;
    const int k_kx  = (u & 1) * 16;
    const int v_row = (u & 1) * 8 + j;
    const int v_dx  = (u >> 1) * 16;

    // K/V staging: 64 rows x 8 chunks = 512 chunks per tensor, 2/thread
    auto stage_kv = [&](int t, int s) {
        const unsigned kb = qs_base + 18432u + (unsigned)s * 18432u;
        const unsigned vb = kb + 9216u;
        const int r0 = t * 64;
        #pragma unroll
        for (int i = 0; i < 2; i++) {
            int ca = tid + i * 256;
            int r = ca >> 3, ch = ca & 7;
            cp16(kb + (unsigned)(r * 144 + ch * 16),
                 K + base + (size_t)(r0 + r) * K_D + ch * 8);
            cp16(vb + (unsigned)(r * 144 + ch * 16),
                 V + base + (size_t)(r0 + r) * K_D + ch * 8);
        }
        CP_COMMIT();
    };

    // prologue: Q (1024 chunks, 4/thread) joins tile-0's commit group
    #pragma unroll
    for (int i = 0; i < 4; i++) {
        int c = tid + i * 256;
        int r = c >> 3, ch = c & 7;
        cp16(qs_base + (unsigned)(r * 144 + ch * 16),
             Q + base + (size_t)(qbase + r) * K_D + ch * 8);
    }
    stage_kv(0, 0);
    stage_kv(1, 1);

    float accO[8][4];
    #pragma unroll
    for (int ni = 0; ni < 8; ni++)
        #pragma unroll
        for (int v = 0; v < 4; v++) accO[ni][v] = 0.f;

    float m0 = -1e30f, m1 = -1e30f, l0 = 0.f, l1 = 0.f;

    const int NT = K_S / 64;   // 32 kv tiles

    for (int it = 0; it < NT; it++) {
        const int buf = it % 3;
        if (it == NT - 1) { CP_WAIT0(); } else { CP_WAIT1(); }
        __syncthreads();
        if (it + 2 < NT) stage_kv(it + 2, (it + 2) % 3);

        const unsigned ks = qs_base + 18432u + (unsigned)buf * 18432u;
        const unsigned vs = ks + 9216u;

        // ---- S = Q K^T : warp tile 16q x 64kv ----
        float accS[8][4];
        #pragma unroll
        for (int ni = 0; ni < 8; ni++)
            #pragma unroll
            for (int v = 0; v < 4; v++) accS[ni][v] = 0.f;

        #pragma unroll
        for (int kt = 0; kt < 4; kt++) {
            uint4 a;
            ldsm_x4(a, qs_base + (unsigned)(q_row * 144 + kt * 32 + q_kx));
            #pragma unroll
            for (int np = 0; np < 4; np++) {
                uint4 bb;
                ldsm_x4(bb, ks + (unsigned)((k_row + np * 16) * 144 + kt * 32 + k_kx));
                mma_f16(accS[2 * np],     a, bb.x, bb.y);
                mma_f16(accS[2 * np + 1], a, bb.z, bb.w);
            }
        }

        // ---- online softmax in exp2 domain (rows lane>>2, +8; quad-local) ----
        float mx0 = -1e30f, mx1 = -1e30f;
        #pragma unroll
        for (int ni = 0; ni < 8; ni++) {
            mx0 = fmaxf(mx0, fmaxf(accS[ni][0], accS[ni][1]));
            mx1 = fmaxf(mx1, fmaxf(accS[ni][2], accS[ni][3]));
        }
        mx0 = fmaxf(mx0, __shfl_xor_sync(0xffffffffu, mx0, 1));
        mx0 = fmaxf(mx0, __shfl_xor_sync(0xffffffffu, mx0, 2));
        mx1 = fmaxf(mx1, __shfl_xor_sync(0xffffffffu, mx1, 1));
        mx1 = fmaxf(mx1, __shfl_xor_sync(0xffffffffu, mx1, 2));

        float mn0 = fmaxf(m0, mx0);
        float mn1 = fmaxf(m1, mx1);
        float alpha0 = ex2f((m0 - mn0) * cl2);
        float alpha1 = ex2f((m1 - mn1) * cl2);
        m0 = mn0; m1 = mn1;
        float mc0 = mn0 * cl2, mc1 = mn1 * cl2;

        float sum0 = 0.f, sum1 = 0.f;
        #pragma unroll
        for (int ni = 0; ni < 8; ni++) {
            accS[ni][0] = ex2f(fmaf(accS[ni][0], cl2, -mc0));
            accS[ni][1] = ex2f(fmaf(accS[ni][1], cl2, -mc0));
            accS[ni][2] = ex2f(fmaf(accS[ni][2], cl2, -mc1));
            accS[ni][3] = ex2f(fmaf(accS[ni][3], cl2, -mc1));
            sum0 += accS[ni][0] + accS[ni][1];
            sum1 += accS[ni][2] + accS[ni][3];
        }
        sum0 += __shfl_xor_sync(0xffffffffu, sum0, 1);
        sum0 += __shfl_xor_sync(0xffffffffu, sum0, 2);
        sum1 += __shfl_xor_sync(0xffffffffu, sum1, 1);
        sum1 += __shfl_xor_sync(0xffffffffu, sum1, 2);
        l0 = l0 * alpha0 + sum0;
        l1 = l1 * alpha1 + sum1;

        #pragma unroll
        for (int ni = 0; ni < 8; ni++) {
            accO[ni][0] *= alpha0; accO[ni][1] *= alpha0;
            accO[ni][2] *= alpha1; accO[ni][3] *= alpha1;
        }

        // ---- O += P @ V : P C-frag f32 pairs -> fp16 A-frag regs ----
        #pragma unroll
        for (int kt = 0; kt < 4; kt++) {
            uint4 aP;
            aP.x = h2u(__floats2half2_rn(accS[2 * kt][0],     accS[2 * kt][1]));
            aP.y = h2u(__floats2half2_rn(accS[2 * kt][2],     accS[2 * kt][3]));
            aP.z = h2u(__floats2half2_rn(accS[2 * kt + 1][0], accS[2 * kt + 1][1]));
            aP.w = h2u(__floats2half2_rn(accS[2 * kt + 1][2], accS[2 * kt + 1][3]));
            #pragma unroll
            for (int np = 0; np < 4; np++) {
                uint4 bb;
                ldsm_x4_t(bb, vs + (unsigned)((kt * 16 + v_row) * 144 + np * 32 + v_dx));
                mma_f16(accO[2 * np],     aP, bb.x, bb.y);
                mma_f16(accO[2 * np + 1], aP, bb.z, bb.w);
            }
        }
    }

    // Epilogue: normalize and write half context
    float inv0 = 1.0f / l0;
    float inv1 = 1.0f / l1;
    int row0 = qbase + warp * 16 + (lane >> 2);
    #pragma unroll
    for (int ni = 0; ni < 8; ni++) {
        int col = ni * 8 + (lane & 3) * 2;
        *(__half2*)&O[base + (size_t)row0 * K_D + col] =
            __floats2half2_rn(accO[ni][0] * inv0, accO[ni][1] * inv0);
        *(__half2*)&O[base + (size_t)(row0 + 8) * K_D + col] =
            __floats2half2_rn(accO[ni][2] * inv1, accO[ni][3] * inv1);
    }
}

// ---------------------------------------------------------------------------
extern "C" void kernel_launch(void* const* d_in, const int* in_sizes, int n_in,
                              void* d_out, int out_size)
{
    const float* query = (const float*)d_in[0];
    const float* key   = (const float*)d_in[1];
    const float* value = (const float*)d_in[2];
    const float* Wq    = (const float*)d_in[3];
    const float* bq    = (const float*)d_in[4];
    const float* Wk    = (const float*)d_in[5];
    const float* bk    = (const float*)d_in[6];
    const float* Wv    = (const float*)d_in[7];
    const float* bv    = (const float*)d_in[8];
    const float* Wo    = (const float*)d_in[9];
    const float* bo    = (const float*)d_in[10];
    float* out = (float*)d_out;

    __half *xq, *xk, *xv, *hwq, *hwk, *hwv, *hwo, *qh, *kh, *vh, *ch;
    cudaGetSymbolAddress((void**)&xq, g_Xq);
    cudaGetSymbolAddress((void**)&xk, g_Xk);
    cudaGetSymbolAddress((void**)&xv, g_Xv);
    cudaGetSymbolAddress((void**)&hwq, g_hWq);
    cudaGetSymbolAddress((void**)&hwk, g_hWk);
    cudaGetSymbolAddress((void**)&hwv, g_hWv);
    cudaGetSymbolAddress((void**)&hwo, g_hWo);
    cudaGetSymbolAddress((void**)&qh, g_Qh);
    cudaGetSymbolAddress((void**)&kh, g_Kh);
    cudaGetSymbolAddress((void**)&vh, g_Vh);
    cudaGetSymbolAddress((void**)&ch, g_Ch);

    static bool attr_done = false;
    if (!attr_done) {
        cudaFuncSetAttribute(gemm_tc<__half>,
                             cudaFuncAttributeMaxDynamicSharedMemorySize, 61440);
        cudaFuncSetAttribute(gemm_tc<float>,
                             cudaFuncAttributeMaxDynamicSharedMemorySize, 61440);
        cudaFuncSetAttribute(flash_tc,
                             cudaFuncAttributeMaxDynamicSharedMemorySize, 73728);
        attr_done = true;
    }

    // 1) convert inputs + weights to half
    dim3 cvt_grid(512, 7);
    cvt_all<<<cvt_grid, 256>>>(query, key, value, Wq, Wk, Wv, Wo,
                               xq, xk, xv, hwq, hwk, hwv, hwo);

    // 2) Q/K/V projections batched in ONE launch (grid.z = 3)
    dim3 gemm_grid3(K_D / 128, K_ROWS / 128, 3);   // (8, 64, 3)
    gemm_tc<__half><<<gemm_grid3, 256, 61440>>>(
        xq, xk, xv, hwq, hwk, hwv, bq, bk, bv, qh, kh, vh);

    // 3) attention (half in, half out)
    dim3 attn_grid(K_B * K_H, K_S / 128);          // (64, 16)
    flash_tc<<<attn_grid, 256, 73728>>>(qh, kh, vh, ch);

    // 4) output projection (half in, float out)
    dim3 gemm_grid1(K_D / 128, K_ROWS / 128, 1);
    gemm_tc<float><<<gemm_grid1, 256, 61440>>>(
        ch, ch, ch, hwo, hwo, hwo, bo, bo, bo, out, out, out);
}

// round 11
// speedup vs baseline: 4.1899x; 1.0764x over previous
#include <cuda_runtime.h>
#include <cuda_fp16.h>
#include <cstdint>

#define K_B 4
#define K_S 2048
#define K_D 1024
#define K_H 16
#define K_DH 64
#define K_ROWS (K_B * K_S)   // 8192

// Half-precision scratch (device globals: allocation-free per harness rules)
__device__ __half g_Xq[K_ROWS * K_D];
__device__ __half g_Xk[K_ROWS * K_D];
__device__ __half g_Xv[K_ROWS * K_D];
__device__ __half g_hWq[K_D * K_D];
__device__ __half g_hWk[K_D * K_D];
__device__ __half g_hWv[K_D * K_D];
__device__ __half g_hWo[K_D * K_D];
__device__ __half g_Qh[K_ROWS * K_D];
__device__ __half g_Kh[K_ROWS * K_D];
__device__ __half g_Vh[K_ROWS * K_D];
__device__ __half g_Ch[K_ROWS * K_D];

// ---------------------------------------------------------------------------
// helpers
// ---------------------------------------------------------------------------
__device__ __forceinline__ unsigned h2u(__half2 h) {
    return *reinterpret_cast<unsigned*>(&h);
}

__device__ __forceinline__ float ex2f(float x) {
    float y;
    asm("ex2.approx.f32 %0, %1;" : "=f"(y) : "f"(x));
    return y;
}

__device__ __forceinline__ void mma_f16(float* d, const uint4 a, unsigned b0, unsigned b1) {
    asm volatile(
        "mma.sync.aligned.m16n8k16.row.col.f32.f16.f16.f32 "
        "{%0,%1,%2,%3}, {%4,%5,%6,%7}, {%8,%9}, {%0,%1,%2,%3};\n"
        : "+f"(d[0]), "+f"(d[1]), "+f"(d[2]), "+f"(d[3])
        : "r"(a.x), "r"(a.y), "r"(a.z), "r"(a.w), "r"(b0), "r"(b1));
}

__device__ __forceinline__ void ldsm_x4(uint4& d, unsigned addr) {
    asm volatile("ldmatrix.sync.aligned.m8n8.x4.shared.b16 {%0,%1,%2,%3}, [%4];"
        : "=r"(d.x), "=r"(d.y), "=r"(d.z), "=r"(d.w) : "r"(addr));
}

__device__ __forceinline__ void ldsm_x4_t(uint4& d, unsigned addr) {
    asm volatile("ldmatrix.sync.aligned.m8n8.x4.trans.shared.b16 {%0,%1,%2,%3}, [%4];"
        : "=r"(d.x), "=r"(d.y), "=r"(d.z), "=r"(d.w) : "r"(addr));
}

__device__ __forceinline__ void cp16(unsigned dst, const void* src) {
    asm volatile("cp.async.cg.shared.global [%0], [%1], 16;\n" :: "r"(dst), "l"(src));
}
#define CP_COMMIT() asm volatile("cp.async.commit_group;\n" ::: "memory")
#define CP_WAIT0()  asm volatile("cp.async.wait_group 0;\n" ::: "memory")
#define CP_WAIT1()  asm volatile("cp.async.wait_group 1;\n" ::: "memory")

#define ONES_F16X2 0x3C003C00u   // (1.0h, 1.0h)

// ---------------------------------------------------------------------------
// Conversion kernel: f32 -> f16 for 3 activations + 4 weight matrices
// ---------------------------------------------------------------------------
__global__ __launch_bounds__(256) void cvt_all(
    const float* s0, const float* s1, const float* s2, const float* s3,
    const float* s4, const float* s5, const float* s6,
    __half* d0, __half* d1, __half* d2, __half* d3,
    __half* d4, __half* d5, __half* d6)
{
    const float* ss[7] = {s0, s1, s2, s3, s4, s5, s6};
    __half* dd[7] = {d0, d1, d2, d3, d4, d5, d6};
    int t = blockIdx.y;
    int n4 = (t < 3) ? (K_ROWS * K_D / 4) : (K_D * K_D / 4);
    const float4* src = (const float4*)ss[t];
    uint2* dst = (uint2*)dd[t];
    for (int i = blockIdx.x * 256 + threadIdx.x; i < n4; i += gridDim.x * 256) {
        float4 v = src[i];
        uint2 w;
        w.x = h2u(__floats2half2_rn(v.x, v.y));
        w.y = h2u(__floats2half2_rn(v.z, v.w));
        dst[i] = w;
    }
}

// ---------------------------------------------------------------------------
// GEMM: out = x @ W^T + bias (half in; out half or float).
// BM=BN=128, BK=64, 256 threads (8 warps), warp tile 32x64.
// 3-stage cp.async pipeline, ONE __syncthreads per 64-wide k-iter.
// Rows padded to 144B (72 halves) for conflict-free ldmatrix.
// Dynamic smem: 3 * (18432 A + 18432 B) = 110592 B. 2 CTAs/SM.
// ---------------------------------------------------------------------------
extern __shared__ unsigned char smem_raw[];

#define G_STRIDE 144u        // bytes per row (64 halves data + 8 pad)
#define G_TILE   18432u      // 128 * 144
#define G_STAGE  36864u      // A + B

template <typename OutT>
__global__ __launch_bounds__(256, 2) void gemm_tc(
    const __half* __restrict__ x0, const __half* __restrict__ x1, const __half* __restrict__ x2,
    const __half* __restrict__ w0, const __half* __restrict__ w1, const __half* __restrict__ w2,
    const float* __restrict__ b0,  const float* __restrict__ b1,  const float* __restrict__ b2,
    OutT* __restrict__ o0, OutT* __restrict__ o1, OutT* __restrict__ o2)
{
    const int z = blockIdx.z;
    const __half* x = (z == 0) ? x0 : (z == 1) ? x1 : x2;
    const __half* W = (z == 0) ? w0 : (z == 1) ? w1 : w2;
    const float* bias = (z == 0) ? b0 : (z == 1) ? b1 : b2;
    OutT* out = (z == 0) ? o0 : (z == 1) ? o1 : o2;

    const int tid  = threadIdx.x;
    const int lane = tid & 31;
    const int warp = tid >> 5;
    const int wm = warp >> 1;   // 0..3 (32 m-rows each)
    const int wn = warp & 1;    // 0..1 (64 n-cols each)
    const int rowBase = blockIdx.y * 128;
    const int colBase = blockIdx.x * 128;

    const unsigned sb = (unsigned)__cvta_generic_to_shared(smem_raw);
    const int u = lane >> 3, j = lane & 7;
    const int a_row = wm * 32 + (u & 1) * 8 + j;
    const int a_kx  = (u >> 1) * 16;
    const int b_row = wn * 64 + (u >> 1) * 8 + j;
    const int b_kx  = (u & 1) * 16;

    // staging: per matrix 1024 chunks (128 rows x 8 x 16B), 4/thread
    auto stage = [&](int t, int s) {
        const unsigned ab = sb + (unsigned)s * G_STAGE;
        const unsigned bb = ab + G_TILE;
        const int k0 = t * 64;
        #pragma unroll
        for (int i = 0; i < 4; i++) {
            int ca = tid + i * 256;        // 0..1023
            int r = ca >> 3, c = ca & 7;
            cp16(ab + (unsigned)(r * G_STRIDE + c * 16),
                 x + (size_t)(rowBase + r) * K_D + k0 + c * 8);
            cp16(bb + (unsigned)(r * G_STRIDE + c * 16),
                 W + (size_t)(colBase + r) * K_D + k0 + c * 8);
        }
        CP_COMMIT();
    };

    float acc[2][8][4];
    #pragma unroll
    for (int mi = 0; mi < 2; mi++)
        #pragma unroll
        for (int ni = 0; ni < 8; ni++)
            #pragma unroll
            for (int v = 0; v < 4; v++) acc[mi][ni][v] = 0.f;

    const int NT = K_D / 64;   // 16 k-tiles
    stage(0, 0);
    stage(1, 1);

    for (int it = 0; it < NT; it++) {
        const int buf = it % 3;
        if (it == NT - 1) { CP_WAIT0(); } else { CP_WAIT1(); }
        __syncthreads();
        if (it + 2 < NT) stage(it + 2, (it + 2) % 3);

        const unsigned ab = sb + (unsigned)buf * G_STAGE;
        const unsigned bb_ = ab + G_TILE;
        #pragma unroll
        for (int kt = 0; kt < 4; kt++) {
            uint4 afr[2];
            #pragma unroll
            for (int mi = 0; mi < 2; mi++)
                ldsm_x4(afr[mi], ab + (unsigned)((a_row + mi * 16) * G_STRIDE + kt * 32 + a_kx));
            #pragma unroll
            for (int np = 0; np < 4; np++) {
                uint4 bb;
                ldsm_x4(bb, bb_ + (unsigned)((b_row + np * 16) * G_STRIDE + kt * 32 + b_kx));
                #pragma unroll
                for (int mi = 0; mi < 2; mi++) {
                    mma_f16(acc[mi][2 * np],     afr[mi], bb.x, bb.y);
                    mma_f16(acc[mi][2 * np + 1], afr[mi], bb.z, bb.w);
                }
            }
        }
    }

    #pragma unroll
    for (int mi = 0; mi < 2; mi++) {
        int row0 = rowBase + (wm * 2 + mi) * 16 + (lane >> 2);
        #pragma unroll
        for (int ni = 0; ni < 8; ni++) {
            int col = colBase + (wn * 8 + ni) * 8 + (lane & 3) * 2;
            float bb0 = __ldg(&bias[col]);
            float bb1 = __ldg(&bias[col + 1]);
            float c00 = acc[mi][ni][0] + bb0, c01 = acc[mi][ni][1] + bb1;
            float c10 = acc[mi][ni][2] + bb0, c11 = acc[mi][ni][3] + bb1;
            if constexpr (sizeof(OutT) == 2) {
                *(__half2*)&out[(size_t)row0 * K_D + col] = __floats2half2_rn(c00, c01);
                *(__half2*)&out[(size_t)(row0 + 8) * K_D + col] = __floats2half2_rn(c10, c11);
            } else {
                *(float2*)&out[(size_t)row0 * K_D + col] = make_float2(c00, c01);
                *(float2*)&out[(size_t)(row0 + 8) * K_D + col] = make_float2(c10, c11);
            }
        }
    }
}

// ---------------------------------------------------------------------------
// Flash attention: fp16 mma.sync, Bc=64, 3-stage cp.async, exp2 softmax,
// row-sum via MMA-with-ones (no FADD/SHFL reduction for l).
// Grid: (B*H, S/128). Block: 256 threads (8 warps), 16 q-rows per warp.
// Dynamic smem: Q 18432 + 3*(K 9216 + V 9216) = 73728 B. 2 CTAs/SM.
// ---------------------------------------------------------------------------
#define FS 72   // half stride (64 data + 8 pad) => 144B rows

__global__ __launch_bounds__(256, 2) void flash_tc(
    const __half* __restrict__ Q, const __half* __restrict__ K,
    const __half* __restrict__ V, __half* __restrict__ O)
{
    const unsigned qs_base = (unsigned)__cvta_generic_to_shared(smem_raw);

    const int tid  = threadIdx.x;
    const int lane = tid & 31;
    const int warp = tid >> 5;

    const int bh = blockIdx.x;
    const int b = bh / K_H, h = bh % K_H;
    const int qbase = blockIdx.y * 128;
    const size_t base = (size_t)b * K_S * K_D + (size_t)h * K_DH;
    const float cl2 = 0.18033688f;   // (1/sqrt(64)) * log2(e)

    const int u = lane >> 3, j = lane & 7;
    const int q_row = warp * 16 + (u & 1) * 8 + j;
    const int q_kx  = (u >> 1) * 16;
    const int k_row = (u >> 1) * 8 + j;
    const int k_kx  = (u & 1) * 16;
    const int v_row = (u & 1) * 8 + j;
    const int v_dx  = (u >> 1) * 16;

    // K/V staging: 64 rows x 8 chunks = 512 chunks per tensor, 2/thread
    auto stage_kv = [&](int t, int s) {
        const unsigned kb = qs_base + 18432u + (unsigned)s * 18432u;
        const unsigned vb = kb + 9216u;
        const int r0 = t * 64;
        #pragma unroll
        for (int i = 0; i < 2; i++) {
            int ca = tid + i * 256;
            int r = ca >> 3, ch = ca & 7;
            cp16(kb + (unsigned)(r * 144 + ch * 16),
                 K + base + (size_t)(r0 + r) * K_D + ch * 8);
            cp16(vb + (unsigned)(r * 144 + ch * 16),
                 V + base + (size_t)(r0 + r) * K_D + ch * 8);
        }
        CP_COMMIT();
    };

    // prologue: Q (1024 chunks, 4/thread) joins tile-0's commit group
    #pragma unroll
    for (int i = 0; i < 4; i++) {
        int c = tid + i * 256;
        int r = c >> 3, ch = c & 7;
        cp16(qs_base + (unsigned)(r * 144 + ch * 16),
             Q + base + (size_t)(qbase + r) * K_D + ch * 8);
    }
    stage_kv(0, 0);
    stage_kv(1, 1);

    float accO[8][4];
    #pragma unroll
    for (int ni = 0; ni < 8; ni++)
        #pragma unroll
        for (int v = 0; v < 4; v++) accO[ni][v] = 0.f;

    float m0 = -1e30f, m1 = -1e30f, l0 = 0.f, l1 = 0.f;

    const int NT = K_S / 64;   // 32 kv tiles

    for (int it = 0; it < NT; it++) {
        const int buf = it % 3;
        if (it == NT - 1) { CP_WAIT0(); } else { CP_WAIT1(); }
        __syncthreads();
        if (it + 2 < NT) stage_kv(it + 2, (it + 2) % 3);

        const unsigned ks = qs_base + 18432u + (unsigned)buf * 18432u;
        const unsigned vs = ks + 9216u;

        // ---- S = Q K^T : warp tile 16q x 64kv ----
        float accS[8][4];
        #pragma unroll
        for (int ni = 0; ni < 8; ni++)
            #pragma unroll
            for (int v = 0; v < 4; v++) accS[ni][v] = 0.f;

        #pragma unroll
        for (int kt = 0; kt < 4; kt++) {
            uint4 a;
            ldsm_x4(a, qs_base + (unsigned)(q_row * 144 + kt * 32 + q_kx));
            #pragma unroll
            for (int np = 0; np < 4; np++) {
                uint4 bb;
                ldsm_x4(bb, ks + (unsigned)((k_row + np * 16) * 144 + kt * 32 + k_kx));
                mma_f16(accS[2 * np],     a, bb.x, bb.y);
                mma_f16(accS[2 * np + 1], a, bb.z, bb.w);
            }
        }

        // ---- online softmax in exp2 domain (rows lane>>2, +8; quad-local) ----
        float mx0 = -1e30f, mx1 = -1e30f;
        #pragma unroll
        for (int ni = 0; ni < 8; ni++) {
            mx0 = fmaxf(mx0, fmaxf(accS[ni][0], accS[ni][1]));
            mx1 = fmaxf(mx1, fmaxf(accS[ni][2], accS[ni][3]));
        }
        mx0 = fmaxf(mx0, __shfl_xor_sync(0xffffffffu, mx0, 1));
        mx0 = fmaxf(mx0, __shfl_xor_sync(0xffffffffu, mx0, 2));
        mx1 = fmaxf(mx1, __shfl_xor_sync(0xffffffffu, mx1, 1));
        mx1 = fmaxf(mx1, __shfl_xor_sync(0xffffffffu, mx1, 2));

        float mn0 = fmaxf(m0, mx0);
        float mn1 = fmaxf(m1, mx1);
        float alpha0 = ex2f((m0 - mn0) * cl2);
        float alpha1 = ex2f((m1 - mn1) * cl2);
        m0 = mn0; m1 = mn1;
        float mc0 = mn0 * cl2, mc1 = mn1 * cl2;

        #pragma unroll
        for (int ni = 0; ni < 8; ni++) {
            accS[ni][0] = ex2f(fmaf(accS[ni][0], cl2, -mc0));
            accS[ni][1] = ex2f(fmaf(accS[ni][1], cl2, -mc0));
            accS[ni][2] = ex2f(fmaf(accS[ni][2], cl2, -mc1));
            accS[ni][3] = ex2f(fmaf(accS[ni][3], cl2, -mc1));
        }

        #pragma unroll
        for (int ni = 0; ni < 8; ni++) {
            accO[ni][0] *= alpha0; accO[ni][1] *= alpha0;
            accO[ni][2] *= alpha1; accO[ni][3] *= alpha1;
        }

        // ---- O += P @ V, plus row-sum via MMA with ones ----
        float accL[4] = {0.f, 0.f, 0.f, 0.f};
        #pragma unroll
        for (int kt = 0; kt < 4; kt++) {
            uint4 aP;
            aP.x = h2u(__floats2half2_rn(accS[2 * kt][0],     accS[2 * kt][1]));
            aP.y = h2u(__floats2half2_rn(accS[2 * kt][2],     accS[2 * kt][3]));
            aP.z = h2u(__floats2half2_rn(accS[2 * kt + 1][0], accS[2 * kt + 1][1]));
            aP.w = h2u(__floats2half2_rn(accS[2 * kt + 1][2], accS[2 * kt + 1][3]));
            mma_f16(accL, aP, ONES_F16X2, ONES_F16X2);   // rowsum: C(r,n) = sum_k P(r,k)
            #pragma unroll
            for (int np = 0; np < 4; np++) {
                uint4 bb;
                ldsm_x4_t(bb, vs + (unsigned)((kt * 16 + v_row) * 144 + np * 32 + v_dx));
                mma_f16(accO[2 * np],     aP, bb.x, bb.y);
                mma_f16(accO[2 * np + 1], aP, bb.z, bb.w);
            }
        }
        l0 = l0 * alpha0 + accL[0];   // same value in all lanes of the row quad
        l1 = l1 * alpha1 + accL[2];
    }

    // Epilogue: normalize and write half context
    float inv0 = 1.0f / l0;
    float inv1 = 1.0f / l1;
    int row0 = qbase + warp * 16 + (lane >> 2);
    #pragma unroll
    for (int ni = 0; ni < 8; ni++) {
        int col = ni * 8 + (lane & 3) * 2;
        *(__half2*)&O[base + (size_t)row0 * K_D + col] =
            __floats2half2_rn(accO[ni][0] * inv0, accO[ni][1] * inv0);
        *(__half2*)&O[base + (size_t)(row0 + 8) * K_D + col] =
            __floats2half2_rn(accO[ni][2] * inv1, accO[ni][3] * inv1);
    }
}

// ---------------------------------------------------------------------------
extern "C" void kernel_launch(void* const* d_in, const int* in_sizes, int n_in,
                              void* d_out, int out_size)
{
    const float* query = (const float*)d_in[0];
    const float* key   = (const float*)d_in[1];
    const float* value = (const float*)d_in[2];
    const float* Wq    = (const float*)d_in[3];
    const float* bq    = (const float*)d_in[4];
    const float* Wk    = (const float*)d_in[5];
    const float* bk    = (const float*)d_in[6];
    const float* Wv    = (const float*)d_in[7];
    const float* bv    = (const float*)d_in[8];
    const float* Wo    = (const float*)d_in[9];
    const float* bo    = (const float*)d_in[10];
    float* out = (float*)d_out;

    __half *xq, *xk, *xv, *hwq, *hwk, *hwv, *hwo, *qh, *kh, *vh, *ch;
    cudaGetSymbolAddress((void**)&xq, g_Xq);
    cudaGetSymbolAddress((void**)&xk, g_Xk);
    cudaGetSymbolAddress((void**)&xv, g_Xv);
    cudaGetSymbolAddress((void**)&hwq, g_hWq);
    cudaGetSymbolAddress((void**)&hwk, g_hWk);
    cudaGetSymbolAddress((void**)&hwv, g_hWv);
    cudaGetSymbolAddress((void**)&hwo, g_hWo);
    cudaGetSymbolAddress((void**)&qh, g_Qh);
    cudaGetSymbolAddress((void**)&kh, g_Kh);
    cudaGetSymbolAddress((void**)&vh, g_Vh);
    cudaGetSymbolAddress((void**)&ch, g_Ch);

    static bool attr_done = false;
    if (!attr_done) {
        cudaFuncSetAttribute(gemm_tc<__half>,
                             cudaFuncAttributeMaxDynamicSharedMemorySize, 110592);
        cudaFuncSetAttribute(gemm_tc<float>,
                             cudaFuncAttributeMaxDynamicSharedMemorySize, 110592);
        cudaFuncSetAttribute(flash_tc,
                             cudaFuncAttributeMaxDynamicSharedMemorySize, 73728);
        attr_done = true;
    }

    // 1) convert inputs + weights to half
    dim3 cvt_grid(512, 7);
    cvt_all<<<cvt_grid, 256>>>(query, key, value, Wq, Wk, Wv, Wo,
                               xq, xk, xv, hwq, hwk, hwv, hwo);

    // 2) Q/K/V projections batched in ONE launch (grid.z = 3)
    dim3 gemm_grid3(K_D / 128, K_ROWS / 128, 3);   // (8, 64, 3)
    gemm_tc<__half><<<gemm_grid3, 256, 110592>>>(
        xq, xk, xv, hwq, hwk, hwv, bq, bk, bv, qh, kh, vh);

    // 3) attention (half in, half out)
    dim3 attn_grid(K_B * K_H, K_S / 128);          // (64, 16)
    flash_tc<<<attn_grid, 256, 73728>>>(qh, kh, vh, ch);

    // 4) output projection (half in, float out)
    dim3 gemm_grid1(K_D / 128, K_ROWS / 128, 1);
    gemm_tc<float><<<gemm_grid1, 256, 110592>>>(
        ch, ch, ch, hwo, hwo, hwo, bo, bo, bo, out, out, out);
}